// round 11
// baseline (speedup 1.0000x reference)
#include <cuda_runtime.h>
#include <cuda_fp16.h>
#include <cstdint>
#include <math.h>

#define BATCH 64
#define CH    512
#define NPIX  256
#define HEADS 8
#define HD    64

// Preconverted operands / intermediates (no cudaMalloc allowed) -------------
__device__ uint32_t g_wqh[1536 * 256], g_wql[1536 * 256];   // qkv_w hi/lo fp16 pairs
__device__ uint32_t g_woh[512 * 256],  g_wol[512 * 256];    // out_w hi/lo
__device__ uint32_t g_xt[(size_t)BATCH * NPIX * 256];       // x^T fp16 [b][p][c]
__device__ uint32_t g_qh[(size_t)BATCH * 512 * 128];        // Q hi [b][d][tok-pairs]
__device__ uint32_t g_ql[(size_t)BATCH * 512 * 128];        // Q lo
__device__ uint32_t g_kv[(size_t)BATCH * 1024 * 128];       // K,V fp16
__device__ uint32_t g_att16[(size_t)BATCH * NPIX * 256];    // O^T fp16 [b][p][c]

// ======================= helpers ==========================================
__device__ __forceinline__ uint32_t smem_to_u32(const void* p) {
    uint32_t a;
    asm("{ .reg .u64 t; cvta.to.shared.u64 t, %1; cvt.u32.u64 %0, t; }"
        : "=r"(a) : "l"(p));
    return a;
}
__device__ __forceinline__ uint32_t h2u(__half2 h) {
    return *reinterpret_cast<uint32_t*>(&h);
}
__device__ __forceinline__ void ldm_x4(uint32_t* r, uint32_t addr) {
    asm volatile("ldmatrix.sync.aligned.m8n8.x4.shared.b16 {%0,%1,%2,%3}, [%4];"
        : "=r"(r[0]), "=r"(r[1]), "=r"(r[2]), "=r"(r[3]) : "r"(addr));
}
__device__ __forceinline__ void ldm_x4_t(uint32_t* r, uint32_t addr) {
    asm volatile("ldmatrix.sync.aligned.m8n8.x4.trans.shared.b16 {%0,%1,%2,%3}, [%4];"
        : "=r"(r[0]), "=r"(r[1]), "=r"(r[2]), "=r"(r[3]) : "r"(addr));
}
__device__ __forceinline__ void mma_f16(float* c, const uint32_t* a,
                                        const uint32_t* b) {
    asm volatile(
        "mma.sync.aligned.m16n8k16.row.col.f32.f16.f16.f32 "
        "{%0,%1,%2,%3}, {%4,%5,%6,%7}, {%8,%9}, {%0,%1,%2,%3};"
        : "+f"(c[0]), "+f"(c[1]), "+f"(c[2]), "+f"(c[3])
        : "r"(a[0]), "r"(a[1]), "r"(a[2]), "r"(a[3]), "r"(b[0]), "r"(b[1]));
}
#define CP16(smem, gptr) \
    asm volatile("cp.async.ca.shared.global [%0], [%1], 16;" \
        :: "r"((uint32_t)(smem)), "l"(gptr) : "memory")
#define CP_COMMIT() asm volatile("cp.async.commit_group;" ::: "memory")
#define CP_WAIT(n)  asm volatile("cp.async.wait_group %0;" :: "n"(n) : "memory")

// exp via FMA pipe, |relerr|<3e-6
__device__ __forceinline__ float fast_exp(float t) {
    float y = t * 1.4426950408889634f;
    y = fmaxf(y, -126.0f);
    int ni = __float2int_rn(y);
    float f = y - (float)ni;
    float p = 1.3333558146428443e-3f;
    p = fmaf(p, f, 9.618129842071803e-3f);
    p = fmaf(p, f, 5.550410866482158e-2f);
    p = fmaf(p, f, 2.402265069591007e-1f);
    p = fmaf(p, f, 6.931471805599453e-1f);
    p = fmaf(p, f, 1.0f);
    return __uint_as_float(__float_as_uint(p) + ((uint32_t)ni << 23));
}

// ---------------------------------------------------------------------------
// Preconvert kernels
// ---------------------------------------------------------------------------
__global__ void convert_w(const float* __restrict__ w, uint32_t* __restrict__ wh,
                          uint32_t* __restrict__ wl, int n) {
    int i = blockIdx.x * 256 + threadIdx.x;
    if (i < n) {
        float2 v = ((const float2*)w)[i];
        __half2 h = __floats2half2_rn(v.x, v.y);
        float2 fh = __half22float2(h);
        __half2 l = __floats2half2_rn(v.x - fh.x, v.y - fh.y);
        wh[i] = h2u(h);
        wl[i] = h2u(l);
    }
}

// x [b][c][p] fp32 -> x^T fp16 [b][p][c] (packed c-pairs)
__global__ __launch_bounds__(256) void convert_x(const float* __restrict__ x,
                                                 uint32_t* __restrict__ xt) {
    __shared__ float t[32][33];
    const int b = blockIdx.z, c0 = blockIdx.y * 32, p0 = blockIdx.x * 32;
    const int tx = threadIdx.x & 31, ty = threadIdx.x >> 5;
    const float* xp = x + ((size_t)b * CH + c0 + ty) * NPIX + p0 + tx;
    #pragma unroll
    for (int i = 0; i < 32; i += 8) t[ty + i][tx] = xp[(size_t)i * NPIX];
    __syncthreads();
    const int p = threadIdx.x >> 3, j0 = threadIdx.x & 7;
    const size_t base = ((size_t)b * NPIX + p0 + p) * 256 + c0 / 2;
    #pragma unroll
    for (int jj = 0; jj < 2; jj++) {
        int j = j0 + jj * 8;
        xt[base + j] = h2u(__floats2half2_rn(t[2 * j][p], t[2 * j + 1][p]));
    }
}

// ---------------------------------------------------------------------------
// GEMM (fp16, A 2-term split, B single): Y = W X + bias
// CTA 64(m) x 128(n), 4 warps (2x2), warp tile 32x64.
// k64 fetch granularity: 8 lanes per 128B row -> full-line coalesced LDG.
// Smem rows 144B stride (odd x16B: conflict-free STS + LDSM).
// ---------------------------------------------------------------------------
#define G_AH 0
#define G_AL 9216
#define G_BH 18432
#define GEMM_SMEM_BYTES 36864

template <int M, bool PACK>
__global__ __launch_bounds__(128) void gemm_v11(
    const uint32_t* __restrict__ Ah, const uint32_t* __restrict__ Al,
    const uint32_t* __restrict__ Bt, const float* __restrict__ bias,
    float* __restrict__ Yf)
{
    __shared__ __align__(128) char smem[GEMM_SMEM_BYTES];
    const uint32_t sb = smem_to_u32(smem);

    const int tid = threadIdx.x;
    const int wid = tid >> 5;
    const int lane = tid & 31;
    const int wm = wid >> 1;
    const int wn = wid & 1;
    const int p0 = blockIdx.x * 128;
    const int m0 = blockIdx.y * 64;
    const int b  = blockIdx.z;

    // LDG mapping: 8 lanes cover one full 128B row-chunk; rows lrow+16p.
    const int lrow = tid >> 3;            // 0..15
    const int lcol = (tid & 7) * 16;      // 0..112
    const char* gAh = (const char*)Ah + (size_t)(m0 + lrow) * 1024 + lcol;
    const char* gAl = (const char*)Al + (size_t)(m0 + lrow) * 1024 + lcol;
    const char* gBt = (const char*)Bt + ((size_t)b * NPIX + p0 + lrow) * 1024 + lcol;
    const uint32_t srow = (uint32_t)lrow * 144 + lcol;

    // ldmatrix addressing (144B stride)
    const uint32_t aoff = (uint32_t)(wm * 32 + (lane & 15)) * 144 + (lane >> 4) * 16;
    const int q = lane >> 3;
    const uint32_t boff =
        (uint32_t)(wn * 64 + ((q >> 1) & 1) * 8 + (lane & 7)) * 144 + (q & 1) * 16;

    float acc[2][8][4];
    #pragma unroll
    for (int mi = 0; mi < 2; mi++)
        #pragma unroll
        for (int nj = 0; nj < 8; nj++)
            #pragma unroll
            for (int e = 0; e < 4; e++) acc[mi][nj][e] = 0.f;

    // prologue: prefetch iteration 0 (16 full-line-coalesced LDG.128)
    uint4 rah[4], ral[4], rbh[8];
    #pragma unroll
    for (int p = 0; p < 4; p++) {
        rah[p] = *(const uint4*)(gAh + (size_t)(16 * p) * 1024);
        ral[p] = *(const uint4*)(gAl + (size_t)(16 * p) * 1024);
    }
    #pragma unroll
    for (int p = 0; p < 8; p++)
        rbh[p] = *(const uint4*)(gBt + (size_t)(16 * p) * 1024);

    #pragma unroll 1
    for (int c = 0; c < 8; c++) {
        // ---- STS current k64 chunk ----
        #pragma unroll
        for (int p = 0; p < 4; p++) {
            const uint32_t so = srow + p * 16 * 144;
            *(uint4*)(smem + G_AH + so) = rah[p];
            *(uint4*)(smem + G_AL + so) = ral[p];
        }
        #pragma unroll
        for (int p = 0; p < 8; p++)
            *(uint4*)(smem + G_BH + srow + p * 16 * 144) = rbh[p];
        __syncthreads();

        // ---- prefetch next chunk (overlaps mma via scoreboard) ----
        if (c < 7) {
            const size_t go = (size_t)(c + 1) * 128;
            #pragma unroll
            for (int p = 0; p < 4; p++) {
                rah[p] = *(const uint4*)(gAh + (size_t)(16 * p) * 1024 + go);
                ral[p] = *(const uint4*)(gAl + (size_t)(16 * p) * 1024 + go);
            }
            #pragma unroll
            for (int p = 0; p < 8; p++)
                rbh[p] = *(const uint4*)(gBt + (size_t)(16 * p) * 1024 + go);
        }

        // ---- compute: 4 k16-steps ----
        #pragma unroll
        for (int ks = 0; ks < 4; ks++) {
            const uint32_t kb = ks * 32;
            uint32_t ah[2][4], al[2][4], bh[4][4];
            ldm_x4(ah[0], sb + G_AH + aoff + kb);
            ldm_x4(ah[1], sb + G_AH + aoff + kb + 16 * 144);
            ldm_x4(al[0], sb + G_AL + aoff + kb);
            ldm_x4(al[1], sb + G_AL + aoff + kb + 16 * 144);
            #pragma unroll
            for (int g = 0; g < 4; g++)
                ldm_x4(bh[g], sb + G_BH + boff + kb + g * 16 * 144);

            #pragma unroll
            for (int mi = 0; mi < 2; mi++)
                #pragma unroll
                for (int nj = 0; nj < 8; nj++) {
                    const uint32_t* bhp = &bh[nj >> 1][(nj & 1) * 2];
                    mma_f16(acc[mi][nj], ah[mi], bhp);
                    mma_f16(acc[mi][nj], al[mi], bhp);
                }
        }
        __syncthreads();
    }

    // ---- epilogue ----
    #pragma unroll
    for (int mi = 0; mi < 2; mi++) {
        const int rr = wm * 32 + mi * 16 + (lane >> 2);
        const int o = m0 + rr;
        const float bv0 = __ldg(&bias[o]);
        const float bv1 = __ldg(&bias[o + 8]);
        if (PACK) {
            const size_t pcol = (size_t)(p0 >> 1) + wn * 32 + (lane & 3);
            if (m0 < 512) {                       // Q rows: split hi/lo
                size_t r0 = ((size_t)b * 512 + o) * 128 + pcol;
                size_t r1 = r0 + 8 * 128;
                #pragma unroll
                for (int nj = 0; nj < 8; nj++) {
                    float v0 = acc[mi][nj][0] + bv0, v1 = acc[mi][nj][1] + bv0;
                    __half2 h = __floats2half2_rn(v0, v1);
                    float2 fh = __half22float2(h);
                    __half2 l = __floats2half2_rn(v0 - fh.x, v1 - fh.y);
                    g_qh[r0 + nj * 4] = h2u(h);
                    g_ql[r0 + nj * 4] = h2u(l);
                    float w0 = acc[mi][nj][2] + bv1, w1 = acc[mi][nj][3] + bv1;
                    __half2 h2 = __floats2half2_rn(w0, w1);
                    float2 fh2 = __half22float2(h2);
                    __half2 l2 = __floats2half2_rn(w0 - fh2.x, w1 - fh2.y);
                    g_qh[r1 + nj * 4] = h2u(h2);
                    g_ql[r1 + nj * 4] = h2u(l2);
                }
            } else {                              // K/V rows: single fp16
                size_t r0 = ((size_t)b * 1024 + (o - 512)) * 128 + pcol;
                size_t r1 = r0 + 8 * 128;
                #pragma unroll
                for (int nj = 0; nj < 8; nj++) {
                    g_kv[r0 + nj * 4] = h2u(
                        __floats2half2_rn(acc[mi][nj][0] + bv0, acc[mi][nj][1] + bv0));
                    g_kv[r1 + nj * 4] = h2u(
                        __floats2half2_rn(acc[mi][nj][2] + bv1, acc[mi][nj][3] + bv1));
                }
            }
        } else {
            float* y0 = Yf + ((size_t)b * M + o) * NPIX + p0 + wn * 64 + (lane & 3) * 2;
            float* y1 = y0 + 8 * NPIX;
            #pragma unroll
            for (int nj = 0; nj < 8; nj++) {
                *(float2*)(y0 + nj * 8) =
                    make_float2(acc[mi][nj][0] + bv0, acc[mi][nj][1] + bv0);
                *(float2*)(y1 + nj * 8) =
                    make_float2(acc[mi][nj][2] + bv1, acc[mi][nj][3] + bv1);
            }
        }
    }
}

// ---------------------------------------------------------------------------
// Attention (fp16 2-term, operands preconverted; verbatim R10).
// ---------------------------------------------------------------------------
#define AT_QH   0
#define AT_QL   9216
#define AT_KH   18432
#define AT_VH   52224
#define AT_REL  86016
#define AT_MAXB 89872
#define AT_SUMB 90384
#define AT_RS   90896
#define AT_SMEM 91152

__global__ __launch_bounds__(256, 1) void attn_mma(const float* __restrict__ rel)
{
    extern __shared__ char sm[];
    float* smf = (float*)sm;
    const uint32_t sb = smem_to_u32(sm);

    const int tid  = threadIdx.x;
    const int lane = tid & 31;
    const int wid  = tid >> 5;
    const int wn   = wid & 3;
    const int wm   = wid >> 2;
    const int n0g  = blockIdx.x * 64;
    const int h    = blockIdx.y;
    const int b    = blockIdx.z;

    const char* qhp = (const char*)g_qh + ((size_t)b * 512 + h * 64) * 512;
    const char* qlp = (const char*)g_ql + ((size_t)b * 512 + h * 64) * 512;
    const char* kp  = (const char*)g_kv + ((size_t)b * 1024 + h * 64) * 512;
    const char* vp  = kp + (size_t)512 * 512;

    #pragma unroll
    for (int it = 0; it < 2; it++) {
        int i = tid + it * 256;
        int d = i >> 3, ch = (i & 7) * 16;
        CP16(sb + AT_QH + d * 144 + ch, qhp + d * 512 + n0g * 2 + ch);
        CP16(sb + AT_QL + d * 144 + ch, qlp + d * 512 + n0g * 2 + ch);
    }
    #pragma unroll
    for (int it = 0; it < 8; it++) {
        int i = tid + it * 256;
        int d = i >> 5, ch = (i & 31) * 16;
        CP16(sb + AT_KH + d * 528 + ch, kp + d * 512 + ch);
        CP16(sb + AT_VH + d * 528 + ch, vp + d * 512 + ch);
    }
    CP_COMMIT();
    for (int i = tid; i < 961; i += 256)
        smf[AT_REL / 4 + i] = rel[h * 961 + i];
    CP_WAIT(0);
    __syncthreads();

    float acc[16][4];
    #pragma unroll
    for (int f = 0; f < 16; f++)
        #pragma unroll
        for (int e = 0; e < 4; e++) acc[f][e] = 0.f;

    const uint32_t a_row = ((lane >> 4) & 1) * 8 + (lane & 7);
    const uint32_t a_col = (uint32_t)(wn * 16 + ((lane >> 3) & 1) * 8) * 2;
    const uint32_t b_row = ((lane >> 3) & 1) * 8 + (lane & 7);
    const uint32_t b_col8 = ((lane >> 4) & 1) * 8;

    #pragma unroll
    for (int s = 0; s < 4; s++) {
        uint32_t ah[4], al[4];
        ldm_x4_t(ah, sb + AT_QH + (s * 16 + a_row) * 144 + a_col);
        ldm_x4_t(al, sb + AT_QL + (s * 16 + a_row) * 144 + a_col);
        #pragma unroll
        for (int mg = 0; mg < 8; mg++) {
            const uint32_t mcol = (uint32_t)(wm * 128 + mg * 16 + b_col8) * 2;
            uint32_t bh[4];
            ldm_x4_t(bh, sb + AT_KH + (s * 16 + b_row) * 528 + mcol);
            mma_f16(acc[2 * mg], ah, &bh[0]);
            mma_f16(acc[2 * mg], al, &bh[0]);
            mma_f16(acc[2 * mg + 1], ah, &bh[2]);
            mma_f16(acc[2 * mg + 1], al, &bh[2]);
        }
    }

    const int rq  = lane >> 2;
    const int nr  = n0g + wn * 16 + rq;
    const int nr8 = nr + 8;
    const int nb0 = (nr >> 4) * 31 + (nr & 15) + 480;
    const int nb8 = (nr8 >> 4) * 31 + (nr8 & 15) + 480;
    const float* Rs = smf + AT_REL / 4;

    float mx0 = -1e30f, mx8 = -1e30f;
    #pragma unroll
    for (int f = 0; f < 16; f++) {
        int mc = wm * 128 + f * 8 + (lane & 3) * 2;
        int mi0 = (mc >> 4) * 31 + (mc & 15);
        int mi1 = ((mc + 1) >> 4) * 31 + ((mc + 1) & 15);
        acc[f][0] = fmaf(acc[f][0], 0.125f, Rs[nb0 - mi0]);
        acc[f][1] = fmaf(acc[f][1], 0.125f, Rs[nb0 - mi1]);
        acc[f][2] = fmaf(acc[f][2], 0.125f, Rs[nb8 - mi0]);
        acc[f][3] = fmaf(acc[f][3], 0.125f, Rs[nb8 - mi1]);
        mx0 = fmaxf(mx0, fmaxf(acc[f][0], acc[f][1]));
        mx8 = fmaxf(mx8, fmaxf(acc[f][2], acc[f][3]));
    }
    mx0 = fmaxf(mx0, __shfl_xor_sync(0xFFFFFFFF, mx0, 1));
    mx0 = fmaxf(mx0, __shfl_xor_sync(0xFFFFFFFF, mx0, 2));
    mx8 = fmaxf(mx8, __shfl_xor_sync(0xFFFFFFFF, mx8, 1));
    mx8 = fmaxf(mx8, __shfl_xor_sync(0xFFFFFFFF, mx8, 2));
    float* maxb = smf + AT_MAXB / 4;
    const int row = wn * 16 + rq;
    if ((lane & 3) == 0) {
        maxb[wm * 64 + row]     = mx0;
        maxb[wm * 64 + row + 8] = mx8;
    }
    __syncthreads();
    mx0 = fmaxf(maxb[row],     maxb[64 + row]);
    mx8 = fmaxf(maxb[row + 8], maxb[64 + row + 8]);

    float s0 = 0.f, s8 = 0.f;
    #pragma unroll
    for (int f = 0; f < 16; f++) {
        acc[f][0] = fast_exp(acc[f][0] - mx0);
        acc[f][1] = fast_exp(acc[f][1] - mx0);
        acc[f][2] = fast_exp(acc[f][2] - mx8);
        acc[f][3] = fast_exp(acc[f][3] - mx8);
        s0 += acc[f][0] + acc[f][1];
        s8 += acc[f][2] + acc[f][3];
    }
    s0 += __shfl_xor_sync(0xFFFFFFFF, s0, 1);
    s0 += __shfl_xor_sync(0xFFFFFFFF, s0, 2);
    s8 += __shfl_xor_sync(0xFFFFFFFF, s8, 1);
    s8 += __shfl_xor_sync(0xFFFFFFFF, s8, 2);
    float* sumb = smf + AT_SUMB / 4;
    if ((lane & 3) == 0) {
        sumb[wm * 64 + row]     = s0;
        sumb[wm * 64 + row + 8] = s8;
    }
    __syncthreads();
    if (wm == 0 && (lane & 3) == 0) {
        smf[AT_RS / 4 + row]     = 1.f / (sumb[row] + sumb[64 + row]);
        smf[AT_RS / 4 + row + 8] = 1.f / (sumb[row + 8] + sumb[64 + row + 8]);
    }

    uint32_t ph[16][2], pl[16][2];
    #pragma unroll
    for (int f = 0; f < 16; f++) {
        __half2 h01 = __floats2half2_rn(acc[f][0], acc[f][1]);
        __half2 h23 = __floats2half2_rn(acc[f][2], acc[f][3]);
        float2 f01 = __half22float2(h01), f23 = __half22float2(h23);
        __half2 l01 = __floats2half2_rn(acc[f][0] - f01.x, acc[f][1] - f01.y);
        __half2 l23 = __floats2half2_rn(acc[f][2] - f23.x, acc[f][3] - f23.y);
        ph[f][0] = h2u(h01);
        ph[f][1] = h2u(h23);
        pl[f][0] = h2u(l01);
        pl[f][1] = h2u(l23);
    }

    float oacc[8][4];
    #pragma unroll
    for (int g = 0; g < 8; g++)
        #pragma unroll
        for (int e = 0; e < 4; e++) oacc[g][e] = 0.f;

    const uint32_t v_row = ((lane >> 4) & 1) * 8 + (lane & 7);
    const uint32_t v_colh = ((lane >> 3) & 1) * 16;

    #pragma unroll
    for (int s = 0; s < 8; s++) {
        uint32_t a_h[4] = {ph[2 * s][0], ph[2 * s][1], ph[2 * s + 1][0], ph[2 * s + 1][1]};
        uint32_t a_l[4] = {pl[2 * s][0], pl[2 * s][1], pl[2 * s + 1][0], pl[2 * s + 1][1]};
        const uint32_t vcol = (uint32_t)(wm * 128 + s * 16) * 2 + v_colh;
        #pragma unroll
        for (int dg = 0; dg < 4; dg++) {
            uint32_t bh[4];
            const uint32_t vaddr = (dg * 16 + v_row) * 528 + vcol;
            ldm_x4(bh, sb + AT_VH + vaddr);
            mma_f16(oacc[2 * dg], a_h, &bh[0]);
            mma_f16(oacc[2 * dg], a_l, &bh[0]);
            mma_f16(oacc[2 * dg + 1], a_h, &bh[2]);
            mma_f16(oacc[2 * dg + 1], a_l, &bh[2]);
        }
    }

    float* Osm = smf;                            // [2][64][68] overlay on dead Q+K
    #pragma unroll
    for (int g = 0; g < 8; g++) {
        int d = g * 8 + (lane & 3) * 2;
        float* q0 = Osm + (wm * 64 + d) * 68 + row;
        float* q1 = Osm + (wm * 64 + d + 1) * 68 + row;
        q0[0] = oacc[g][0];
        q1[0] = oacc[g][1];
        q0[8] = oacc[g][2];
        q1[8] = oacc[g][3];
    }
    __syncthreads();

    {
        const int n  = tid >> 2;
        const int dq = tid & 3;
        const float rsv = smf[AT_RS / 4 + n];
        const size_t obase = ((size_t)b * NPIX + n0g + n) * 256 + h * 32 + dq * 8;
        #pragma unroll
        for (int j = 0; j < 8; j++) {
            int d0 = dq * 16 + 2 * j;
            float o0 = (Osm[d0 * 68 + n] + Osm[(64 + d0) * 68 + n]) * rsv;
            float o1 = (Osm[(d0 + 1) * 68 + n] + Osm[(64 + d0 + 1) * 68 + n]) * rsv;
            g_att16[obase + j] = h2u(__floats2half2_rn(o0, o1));
        }
    }
}

// ---------------------------------------------------------------------------
extern "C" void kernel_launch(void* const* d_in, const int* in_sizes, int n_in,
                              void* d_out, int out_size)
{
    const float* x      = (const float*)d_in[0];
    const float* qkv_w  = (const float*)d_in[1];
    const float* qkv_b  = (const float*)d_in[2];
    const float* out_w  = (const float*)d_in[3];
    const float* out_b  = (const float*)d_in[4];
    const float* rel    = (const float*)d_in[5];
    float* out = (float*)d_out;

    void *wqh, *wql, *woh, *wol, *xt, *att16;
    cudaGetSymbolAddress(&wqh, g_wqh);
    cudaGetSymbolAddress(&wql, g_wql);
    cudaGetSymbolAddress(&woh, g_woh);
    cudaGetSymbolAddress(&wol, g_wol);
    cudaGetSymbolAddress(&xt, g_xt);
    cudaGetSymbolAddress(&att16, g_att16);

    cudaFuncSetAttribute(attn_mma,
                         cudaFuncAttributeMaxDynamicSharedMemorySize, AT_SMEM);

    // 0) preconvert (tiny)
    convert_w<<<1536, 256>>>(qkv_w, (uint32_t*)wqh, (uint32_t*)wql, 1536 * 256);
    convert_w<<<512, 256>>>(out_w, (uint32_t*)woh, (uint32_t*)wol, 512 * 256);
    convert_x<<<dim3(NPIX / 32, CH / 32, BATCH), 256>>>(x, (uint32_t*)xt);

    // 1) QKV projection -> Q hi/lo + K/V fp16 (attention layout)
    gemm_v11<3 * CH, true><<<dim3(NPIX / 128, 1536 / 64, BATCH), 128>>>(
        (const uint32_t*)wqh, (const uint32_t*)wql, (const uint32_t*)xt,
        qkv_b, nullptr);

    // 2) Attention -> O^T fp16
    attn_mma<<<dim3(NPIX / 64, HEADS, BATCH), 256, AT_SMEM>>>(rel);

    // 3) Output projection -> fp32 (+bias)
    gemm_v11<CH, false><<<dim3(NPIX / 128, CH / 64, BATCH), 128>>>(
        (const uint32_t*)woh, (const uint32_t*)wol, (const uint32_t*)att16,
        out_b, out);
}

// round 12
// speedup vs baseline: 1.5313x; 1.5313x over previous
#include <cuda_runtime.h>
#include <cuda_fp16.h>
#include <cstdint>
#include <math.h>

#define BATCH 64
#define CH    512
#define NPIX  256
#define HEADS 8
#define HD    64

// Preconverted operands / intermediates (no cudaMalloc allowed) -------------
__device__ uint32_t g_wqh[1536 * 256], g_wql[1536 * 256];   // qkv_w hi/lo fp16 pairs
__device__ uint32_t g_woh[512 * 256],  g_wol[512 * 256];    // out_w hi/lo
__device__ uint32_t g_xt[(size_t)BATCH * NPIX * 256];       // x^T fp16 [b][p][c]
__device__ uint32_t g_qh[(size_t)BATCH * 512 * 128];        // Q hi [b][d][tok-pairs]
__device__ uint32_t g_ql[(size_t)BATCH * 512 * 128];        // Q lo
__device__ uint32_t g_kv[(size_t)BATCH * 1024 * 128];       // K,V fp16
__device__ uint32_t g_att16[(size_t)BATCH * NPIX * 256];    // O^T fp16 [b][p][c]

// ======================= helpers ==========================================
__device__ __forceinline__ uint32_t smem_to_u32(const void* p) {
    uint32_t a;
    asm("{ .reg .u64 t; cvta.to.shared.u64 t, %1; cvt.u32.u64 %0, t; }"
        : "=r"(a) : "l"(p));
    return a;
}
__device__ __forceinline__ uint32_t h2u(__half2 h) {
    return *reinterpret_cast<uint32_t*>(&h);
}
__device__ __forceinline__ void ldm_x4(uint32_t* r, uint32_t addr) {
    asm volatile("ldmatrix.sync.aligned.m8n8.x4.shared.b16 {%0,%1,%2,%3}, [%4];"
        : "=r"(r[0]), "=r"(r[1]), "=r"(r[2]), "=r"(r[3]) : "r"(addr));
}
__device__ __forceinline__ void ldm_x4_t(uint32_t* r, uint32_t addr) {
    asm volatile("ldmatrix.sync.aligned.m8n8.x4.trans.shared.b16 {%0,%1,%2,%3}, [%4];"
        : "=r"(r[0]), "=r"(r[1]), "=r"(r[2]), "=r"(r[3]) : "r"(addr));
}
__device__ __forceinline__ void mma_f16(float* c, const uint32_t* a,
                                        const uint32_t* b) {
    asm volatile(
        "mma.sync.aligned.m16n8k16.row.col.f32.f16.f16.f32 "
        "{%0,%1,%2,%3}, {%4,%5,%6,%7}, {%8,%9}, {%0,%1,%2,%3};"
        : "+f"(c[0]), "+f"(c[1]), "+f"(c[2]), "+f"(c[3])
        : "r"(a[0]), "r"(a[1]), "r"(a[2]), "r"(a[3]), "r"(b[0]), "r"(b[1]));
}
#define CP16(smem, gptr) \
    asm volatile("cp.async.ca.shared.global [%0], [%1], 16;" \
        :: "r"((uint32_t)(smem)), "l"(gptr) : "memory")
#define CP_COMMIT() asm volatile("cp.async.commit_group;" ::: "memory")
#define CP_WAIT(n)  asm volatile("cp.async.wait_group %0;" :: "n"(n) : "memory")

// exp via FMA pipe, |relerr|<3e-6
__device__ __forceinline__ float fast_exp(float t) {
    float y = t * 1.4426950408889634f;
    y = fmaxf(y, -126.0f);
    int ni = __float2int_rn(y);
    float f = y - (float)ni;
    float p = 1.3333558146428443e-3f;
    p = fmaf(p, f, 9.618129842071803e-3f);
    p = fmaf(p, f, 5.550410866482158e-2f);
    p = fmaf(p, f, 2.402265069591007e-1f);
    p = fmaf(p, f, 6.931471805599453e-1f);
    p = fmaf(p, f, 1.0f);
    return __uint_as_float(__float_as_uint(p) + ((uint32_t)ni << 23));
}

// ---------------------------------------------------------------------------
// Preconvert kernels
// ---------------------------------------------------------------------------
__global__ void convert_w(const float* __restrict__ w, uint32_t* __restrict__ wh,
                          uint32_t* __restrict__ wl, int n) {
    int i = blockIdx.x * 256 + threadIdx.x;
    if (i < n) {
        float2 v = ((const float2*)w)[i];
        __half2 h = __floats2half2_rn(v.x, v.y);
        float2 fh = __half22float2(h);
        __half2 l = __floats2half2_rn(v.x - fh.x, v.y - fh.y);
        wh[i] = h2u(h);
        wl[i] = h2u(l);
    }
}

// x [b][c][p] fp32 -> x^T fp16 [b][p][c] (packed c-pairs)
__global__ __launch_bounds__(256) void convert_x(const float* __restrict__ x,
                                                 uint32_t* __restrict__ xt) {
    __shared__ float t[32][33];
    const int b = blockIdx.z, c0 = blockIdx.y * 32, p0 = blockIdx.x * 32;
    const int tx = threadIdx.x & 31, ty = threadIdx.x >> 5;
    const float* xp = x + ((size_t)b * CH + c0 + ty) * NPIX + p0 + tx;
    #pragma unroll
    for (int i = 0; i < 32; i += 8) t[ty + i][tx] = xp[(size_t)i * NPIX];
    __syncthreads();
    const int p = threadIdx.x >> 3, j0 = threadIdx.x & 7;
    const size_t base = ((size_t)b * NPIX + p0 + p) * 256 + c0 / 2;
    #pragma unroll
    for (int jj = 0; jj < 2; jj++) {
        int j = j0 + jj * 8;
        xt[base + j] = h2u(__floats2half2_rn(t[2 * j][p], t[2 * j + 1][p]));
    }
}

// ---------------------------------------------------------------------------
// GEMM (fp16, A 2-term split, B single): Y = W X + bias
// CTA 64x64, 4 warps (2x2), warp tile 32x32 (R10 shape).
// k64 fetch, full-line coalesced LDG, 144B smem rows.
// DOUBLE-BUFFERED smem: one __syncthreads per k64 iteration.
// ---------------------------------------------------------------------------
#define G_AH 0
#define G_AL 9216
#define G_BH 18432
#define G_BUF 27648

template <int M, bool PACK>
__global__ __launch_bounds__(128) void gemm_v12(
    const uint32_t* __restrict__ Ah, const uint32_t* __restrict__ Al,
    const uint32_t* __restrict__ Bt, const float* __restrict__ bias,
    float* __restrict__ Yf)
{
    __shared__ __align__(128) char smem[2 * G_BUF];
    const uint32_t sb = smem_to_u32(smem);

    const int tid = threadIdx.x;
    const int wid = tid >> 5;
    const int lane = tid & 31;
    const int wm = wid >> 1;
    const int wn = wid & 1;
    const int p0 = blockIdx.x * 64;
    const int m0 = blockIdx.y * 64;
    const int b  = blockIdx.z;

    // LDG mapping: 8 lanes cover one full 128B row-chunk; rows lrow+16p.
    const int lrow = tid >> 3;            // 0..15
    const int lcol = (tid & 7) * 16;      // 0..112
    const char* gAh = (const char*)Ah + (size_t)(m0 + lrow) * 1024 + lcol;
    const char* gAl = (const char*)Al + (size_t)(m0 + lrow) * 1024 + lcol;
    const char* gBt = (const char*)Bt + ((size_t)b * NPIX + p0 + lrow) * 1024 + lcol;
    const uint32_t srow = (uint32_t)lrow * 144 + lcol;

    // ldmatrix addressing (144B stride)
    const uint32_t aoff = (uint32_t)(wm * 32 + (lane & 15)) * 144 + (lane >> 4) * 16;
    const int q = lane >> 3;
    const uint32_t boff =
        (uint32_t)(wn * 32 + ((q >> 1) & 1) * 8 + (lane & 7)) * 144 + (q & 1) * 16;

    float acc[2][4][4];
    #pragma unroll
    for (int mi = 0; mi < 2; mi++)
        #pragma unroll
        for (int nj = 0; nj < 4; nj++)
            #pragma unroll
            for (int e = 0; e < 4; e++) acc[mi][nj][e] = 0.f;

    uint4 rah[4], ral[4], rbh[4];
    // prologue: chunk0 -> regs -> buf0; chunk1 -> regs
    #pragma unroll
    for (int p = 0; p < 4; p++) {
        rah[p] = *(const uint4*)(gAh + (size_t)(16 * p) * 1024);
        ral[p] = *(const uint4*)(gAl + (size_t)(16 * p) * 1024);
        rbh[p] = *(const uint4*)(gBt + (size_t)(16 * p) * 1024);
    }
    #pragma unroll
    for (int p = 0; p < 4; p++) {
        const uint32_t so = srow + p * 16 * 144;
        *(uint4*)(smem + G_AH + so) = rah[p];
        *(uint4*)(smem + G_AL + so) = ral[p];
        *(uint4*)(smem + G_BH + so) = rbh[p];
    }
    #pragma unroll
    for (int p = 0; p < 4; p++) {
        rah[p] = *(const uint4*)(gAh + (size_t)(16 * p) * 1024 + 128);
        ral[p] = *(const uint4*)(gAl + (size_t)(16 * p) * 1024 + 128);
        rbh[p] = *(const uint4*)(gBt + (size_t)(16 * p) * 1024 + 128);
    }

    #pragma unroll 1
    for (int c = 0; c < 8; c++) {
        __syncthreads();                         // buf (c&1) ready for all

        // STS chunk c+1 into the OTHER buffer (overlaps this iter's compute)
        if (c < 7) {
            const uint32_t bufo = ((c + 1) & 1) * G_BUF;
            #pragma unroll
            for (int p = 0; p < 4; p++) {
                const uint32_t so = bufo + srow + p * 16 * 144;
                *(uint4*)(smem + G_AH + so) = rah[p];
                *(uint4*)(smem + G_AL + so) = ral[p];
                *(uint4*)(smem + G_BH + so) = rbh[p];
            }
        }
        // LDG chunk c+2 into regs (overlaps compute via scoreboard)
        if (c < 6) {
            const size_t go = (size_t)(c + 2) * 128;
            #pragma unroll
            for (int p = 0; p < 4; p++) {
                rah[p] = *(const uint4*)(gAh + (size_t)(16 * p) * 1024 + go);
                ral[p] = *(const uint4*)(gAl + (size_t)(16 * p) * 1024 + go);
                rbh[p] = *(const uint4*)(gBt + (size_t)(16 * p) * 1024 + go);
            }
        }

        // ---- compute from buf (c&1): 4 k16-steps ----
        const uint32_t stb = sb + (c & 1) * G_BUF;
        #pragma unroll
        for (int ks = 0; ks < 4; ks++) {
            const uint32_t kb = ks * 32;
            uint32_t ah[2][4], al[2][4], bh[2][4];
            ldm_x4(ah[0], stb + G_AH + aoff + kb);
            ldm_x4(ah[1], stb + G_AH + aoff + kb + 16 * 144);
            ldm_x4(al[0], stb + G_AL + aoff + kb);
            ldm_x4(al[1], stb + G_AL + aoff + kb + 16 * 144);
            ldm_x4(bh[0], stb + G_BH + boff + kb);
            ldm_x4(bh[1], stb + G_BH + boff + kb + 16 * 144);

            #pragma unroll
            for (int mi = 0; mi < 2; mi++)
                #pragma unroll
                for (int nj = 0; nj < 4; nj++) {
                    const uint32_t* bhp = &bh[nj >> 1][(nj & 1) * 2];
                    mma_f16(acc[mi][nj], ah[mi], bhp);
                    mma_f16(acc[mi][nj], al[mi], bhp);
                }
        }
    }

    // ---- epilogue ----
    #pragma unroll
    for (int mi = 0; mi < 2; mi++) {
        const int rr = wm * 32 + mi * 16 + (lane >> 2);
        const int o = m0 + rr;
        const float bv0 = __ldg(&bias[o]);
        const float bv1 = __ldg(&bias[o + 8]);
        if (PACK) {
            const size_t pcol = (size_t)(p0 >> 1) + wn * 16 + (lane & 3);
            if (m0 < 512) {                       // Q rows: split hi/lo
                size_t r0 = ((size_t)b * 512 + o) * 128 + pcol;
                size_t r1 = r0 + 8 * 128;
                #pragma unroll
                for (int nj = 0; nj < 4; nj++) {
                    float v0 = acc[mi][nj][0] + bv0, v1 = acc[mi][nj][1] + bv0;
                    __half2 h = __floats2half2_rn(v0, v1);
                    float2 fh = __half22float2(h);
                    __half2 l = __floats2half2_rn(v0 - fh.x, v1 - fh.y);
                    g_qh[r0 + nj * 4] = h2u(h);
                    g_ql[r0 + nj * 4] = h2u(l);
                    float w0 = acc[mi][nj][2] + bv1, w1 = acc[mi][nj][3] + bv1;
                    __half2 h2 = __floats2half2_rn(w0, w1);
                    float2 fh2 = __half22float2(h2);
                    __half2 l2 = __floats2half2_rn(w0 - fh2.x, w1 - fh2.y);
                    g_qh[r1 + nj * 4] = h2u(h2);
                    g_ql[r1 + nj * 4] = h2u(l2);
                }
            } else {                              // K/V rows: single fp16
                size_t r0 = ((size_t)b * 1024 + (o - 512)) * 128 + pcol;
                size_t r1 = r0 + 8 * 128;
                #pragma unroll
                for (int nj = 0; nj < 4; nj++) {
                    g_kv[r0 + nj * 4] = h2u(
                        __floats2half2_rn(acc[mi][nj][0] + bv0, acc[mi][nj][1] + bv0));
                    g_kv[r1 + nj * 4] = h2u(
                        __floats2half2_rn(acc[mi][nj][2] + bv1, acc[mi][nj][3] + bv1));
                }
            }
        } else {
            float* y0 = Yf + ((size_t)b * M + o) * NPIX + p0 + wn * 32 + (lane & 3) * 2;
            float* y1 = y0 + 8 * NPIX;
            #pragma unroll
            for (int nj = 0; nj < 4; nj++) {
                *(float2*)(y0 + nj * 8) =
                    make_float2(acc[mi][nj][0] + bv0, acc[mi][nj][1] + bv0);
                *(float2*)(y1 + nj * 8) =
                    make_float2(acc[mi][nj][2] + bv1, acc[mi][nj][3] + bv1);
            }
        }
    }
}

// ---------------------------------------------------------------------------
// Attention (fp16 2-term; R10 logic, now 2 CTAs/SM via launch_bounds).
// ---------------------------------------------------------------------------
#define AT_QH   0
#define AT_QL   9216
#define AT_KH   18432
#define AT_VH   52224
#define AT_REL  86016
#define AT_MAXB 89872
#define AT_SUMB 90384
#define AT_RS   90896
#define AT_SMEM 91152

__global__ __launch_bounds__(256, 2) void attn_mma(const float* __restrict__ rel)
{
    extern __shared__ char sm[];
    float* smf = (float*)sm;
    const uint32_t sb = smem_to_u32(sm);

    const int tid  = threadIdx.x;
    const int lane = tid & 31;
    const int wid  = tid >> 5;
    const int wn   = wid & 3;
    const int wm   = wid >> 2;
    const int n0g  = blockIdx.x * 64;
    const int h    = blockIdx.y;
    const int b    = blockIdx.z;

    const char* qhp = (const char*)g_qh + ((size_t)b * 512 + h * 64) * 512;
    const char* qlp = (const char*)g_ql + ((size_t)b * 512 + h * 64) * 512;
    const char* kp  = (const char*)g_kv + ((size_t)b * 1024 + h * 64) * 512;
    const char* vp  = kp + (size_t)512 * 512;

    #pragma unroll
    for (int it = 0; it < 2; it++) {
        int i = tid + it * 256;
        int d = i >> 3, ch = (i & 7) * 16;
        CP16(sb + AT_QH + d * 144 + ch, qhp + d * 512 + n0g * 2 + ch);
        CP16(sb + AT_QL + d * 144 + ch, qlp + d * 512 + n0g * 2 + ch);
    }
    #pragma unroll
    for (int it = 0; it < 8; it++) {
        int i = tid + it * 256;
        int d = i >> 5, ch = (i & 31) * 16;
        CP16(sb + AT_KH + d * 528 + ch, kp + d * 512 + ch);
        CP16(sb + AT_VH + d * 528 + ch, vp + d * 512 + ch);
    }
    CP_COMMIT();
    for (int i = tid; i < 961; i += 256)
        smf[AT_REL / 4 + i] = rel[h * 961 + i];
    CP_WAIT(0);
    __syncthreads();

    float acc[16][4];
    #pragma unroll
    for (int f = 0; f < 16; f++)
        #pragma unroll
        for (int e = 0; e < 4; e++) acc[f][e] = 0.f;

    const uint32_t a_row = ((lane >> 4) & 1) * 8 + (lane & 7);
    const uint32_t a_col = (uint32_t)(wn * 16 + ((lane >> 3) & 1) * 8) * 2;
    const uint32_t b_row = ((lane >> 3) & 1) * 8 + (lane & 7);
    const uint32_t b_col8 = ((lane >> 4) & 1) * 8;

    #pragma unroll
    for (int s = 0; s < 4; s++) {
        uint32_t ah[4], al[4];
        ldm_x4_t(ah, sb + AT_QH + (s * 16 + a_row) * 144 + a_col);
        ldm_x4_t(al, sb + AT_QL + (s * 16 + a_row) * 144 + a_col);
        #pragma unroll
        for (int mg = 0; mg < 8; mg++) {
            const uint32_t mcol = (uint32_t)(wm * 128 + mg * 16 + b_col8) * 2;
            uint32_t bh[4];
            ldm_x4_t(bh, sb + AT_KH + (s * 16 + b_row) * 528 + mcol);
            mma_f16(acc[2 * mg], ah, &bh[0]);
            mma_f16(acc[2 * mg], al, &bh[0]);
            mma_f16(acc[2 * mg + 1], ah, &bh[2]);
            mma_f16(acc[2 * mg + 1], al, &bh[2]);
        }
    }

    const int rq  = lane >> 2;
    const int nr  = n0g + wn * 16 + rq;
    const int nr8 = nr + 8;
    const int nb0 = (nr >> 4) * 31 + (nr & 15) + 480;
    const int nb8 = (nr8 >> 4) * 31 + (nr8 & 15) + 480;
    const float* Rs = smf + AT_REL / 4;

    float mx0 = -1e30f, mx8 = -1e30f;
    #pragma unroll
    for (int f = 0; f < 16; f++) {
        int mc = wm * 128 + f * 8 + (lane & 3) * 2;
        int mi0 = (mc >> 4) * 31 + (mc & 15);
        int mi1 = ((mc + 1) >> 4) * 31 + ((mc + 1) & 15);
        acc[f][0] = fmaf(acc[f][0], 0.125f, Rs[nb0 - mi0]);
        acc[f][1] = fmaf(acc[f][1], 0.125f, Rs[nb0 - mi1]);
        acc[f][2] = fmaf(acc[f][2], 0.125f, Rs[nb8 - mi0]);
        acc[f][3] = fmaf(acc[f][3], 0.125f, Rs[nb8 - mi1]);
        mx0 = fmaxf(mx0, fmaxf(acc[f][0], acc[f][1]));
        mx8 = fmaxf(mx8, fmaxf(acc[f][2], acc[f][3]));
    }
    mx0 = fmaxf(mx0, __shfl_xor_sync(0xFFFFFFFF, mx0, 1));
    mx0 = fmaxf(mx0, __shfl_xor_sync(0xFFFFFFFF, mx0, 2));
    mx8 = fmaxf(mx8, __shfl_xor_sync(0xFFFFFFFF, mx8, 1));
    mx8 = fmaxf(mx8, __shfl_xor_sync(0xFFFFFFFF, mx8, 2));
    float* maxb = smf + AT_MAXB / 4;
    const int row = wn * 16 + rq;
    if ((lane & 3) == 0) {
        maxb[wm * 64 + row]     = mx0;
        maxb[wm * 64 + row + 8] = mx8;
    }
    __syncthreads();
    mx0 = fmaxf(maxb[row],     maxb[64 + row]);
    mx8 = fmaxf(maxb[row + 8], maxb[64 + row + 8]);

    float s0 = 0.f, s8 = 0.f;
    #pragma unroll
    for (int f = 0; f < 16; f++) {
        acc[f][0] = fast_exp(acc[f][0] - mx0);
        acc[f][1] = fast_exp(acc[f][1] - mx0);
        acc[f][2] = fast_exp(acc[f][2] - mx8);
        acc[f][3] = fast_exp(acc[f][3] - mx8);
        s0 += acc[f][0] + acc[f][1];
        s8 += acc[f][2] + acc[f][3];
    }
    s0 += __shfl_xor_sync(0xFFFFFFFF, s0, 1);
    s0 += __shfl_xor_sync(0xFFFFFFFF, s0, 2);
    s8 += __shfl_xor_sync(0xFFFFFFFF, s8, 1);
    s8 += __shfl_xor_sync(0xFFFFFFFF, s8, 2);
    float* sumb = smf + AT_SUMB / 4;
    if ((lane & 3) == 0) {
        sumb[wm * 64 + row]     = s0;
        sumb[wm * 64 + row + 8] = s8;
    }
    __syncthreads();
    if (wm == 0 && (lane & 3) == 0) {
        smf[AT_RS / 4 + row]     = 1.f / (sumb[row] + sumb[64 + row]);
        smf[AT_RS / 4 + row + 8] = 1.f / (sumb[row + 8] + sumb[64 + row + 8]);
    }

    uint32_t ph[16][2], pl[16][2];
    #pragma unroll
    for (int f = 0; f < 16; f++) {
        __half2 h01 = __floats2half2_rn(acc[f][0], acc[f][1]);
        __half2 h23 = __floats2half2_rn(acc[f][2], acc[f][3]);
        float2 f01 = __half22float2(h01), f23 = __half22float2(h23);
        __half2 l01 = __floats2half2_rn(acc[f][0] - f01.x, acc[f][1] - f01.y);
        __half2 l23 = __floats2half2_rn(acc[f][2] - f23.x, acc[f][3] - f23.y);
        ph[f][0] = h2u(h01);
        ph[f][1] = h2u(h23);
        pl[f][0] = h2u(l01);
        pl[f][1] = h2u(l23);
    }

    float oacc[8][4];
    #pragma unroll
    for (int g = 0; g < 8; g++)
        #pragma unroll
        for (int e = 0; e < 4; e++) oacc[g][e] = 0.f;

    const uint32_t v_row = ((lane >> 4) & 1) * 8 + (lane & 7);
    const uint32_t v_colh = ((lane >> 3) & 1) * 16;

    #pragma unroll
    for (int s = 0; s < 8; s++) {
        uint32_t a_h[4] = {ph[2 * s][0], ph[2 * s][1], ph[2 * s + 1][0], ph[2 * s + 1][1]};
        uint32_t a_l[4] = {pl[2 * s][0], pl[2 * s][1], pl[2 * s + 1][0], pl[2 * s + 1][1]};
        const uint32_t vcol = (uint32_t)(wm * 128 + s * 16) * 2 + v_colh;
        #pragma unroll
        for (int dg = 0; dg < 4; dg++) {
            uint32_t bh[4];
            const uint32_t vaddr = (dg * 16 + v_row) * 528 + vcol;
            ldm_x4(bh, sb + AT_VH + vaddr);
            mma_f16(oacc[2 * dg], a_h, &bh[0]);
            mma_f16(oacc[2 * dg], a_l, &bh[0]);
            mma_f16(oacc[2 * dg + 1], a_h, &bh[2]);
            mma_f16(oacc[2 * dg + 1], a_l, &bh[2]);
        }
    }

    float* Osm = smf;                            // [2][64][68] overlay on dead Q+K
    #pragma unroll
    for (int g = 0; g < 8; g++) {
        int d = g * 8 + (lane & 3) * 2;
        float* q0 = Osm + (wm * 64 + d) * 68 + row;
        float* q1 = Osm + (wm * 64 + d + 1) * 68 + row;
        q0[0] = oacc[g][0];
        q1[0] = oacc[g][1];
        q0[8] = oacc[g][2];
        q1[8] = oacc[g][3];
    }
    __syncthreads();

    {
        const int n  = tid >> 2;
        const int dq = tid & 3;
        const float rsv = smf[AT_RS / 4 + n];
        const size_t obase = ((size_t)b * NPIX + n0g + n) * 256 + h * 32 + dq * 8;
        #pragma unroll
        for (int j = 0; j < 8; j++) {
            int d0 = dq * 16 + 2 * j;
            float o0 = (Osm[d0 * 68 + n] + Osm[(64 + d0) * 68 + n]) * rsv;
            float o1 = (Osm[(d0 + 1) * 68 + n] + Osm[(64 + d0 + 1) * 68 + n]) * rsv;
            g_att16[obase + j] = h2u(__floats2half2_rn(o0, o1));
        }
    }
}

// ---------------------------------------------------------------------------
extern "C" void kernel_launch(void* const* d_in, const int* in_sizes, int n_in,
                              void* d_out, int out_size)
{
    const float* x      = (const float*)d_in[0];
    const float* qkv_w  = (const float*)d_in[1];
    const float* qkv_b  = (const float*)d_in[2];
    const float* out_w  = (const float*)d_in[3];
    const float* out_b  = (const float*)d_in[4];
    const float* rel    = (const float*)d_in[5];
    float* out = (float*)d_out;

    void *wqh, *wql, *woh, *wol, *xt, *att16;
    cudaGetSymbolAddress(&wqh, g_wqh);
    cudaGetSymbolAddress(&wql, g_wql);
    cudaGetSymbolAddress(&woh, g_woh);
    cudaGetSymbolAddress(&wol, g_wol);
    cudaGetSymbolAddress(&xt, g_xt);
    cudaGetSymbolAddress(&att16, g_att16);

    cudaFuncSetAttribute(attn_mma,
                         cudaFuncAttributeMaxDynamicSharedMemorySize, AT_SMEM);

    // 0) preconvert (tiny)
    convert_w<<<1536, 256>>>(qkv_w, (uint32_t*)wqh, (uint32_t*)wql, 1536 * 256);
    convert_w<<<512, 256>>>(out_w, (uint32_t*)woh, (uint32_t*)wol, 512 * 256);
    convert_x<<<dim3(NPIX / 32, CH / 32, BATCH), 256>>>(x, (uint32_t*)xt);

    // 1) QKV projection -> Q hi/lo + K/V fp16 (attention layout)
    gemm_v12<3 * CH, true><<<dim3(NPIX / 64, 1536 / 64, BATCH), 128>>>(
        (const uint32_t*)wqh, (const uint32_t*)wql, (const uint32_t*)xt,
        qkv_b, nullptr);

    // 2) Attention -> O^T fp16
    attn_mma<<<dim3(NPIX / 64, HEADS, BATCH), 256, AT_SMEM>>>(rel);

    // 3) Output projection -> fp32 (+bias)
    gemm_v12<CH, false><<<dim3(NPIX / 64, CH / 64, BATCH), 128>>>(
        (const uint32_t*)woh, (const uint32_t*)wol, (const uint32_t*)att16,
        out_b, out);
}

// round 13
// speedup vs baseline: 1.6000x; 1.0449x over previous
#include <cuda_runtime.h>
#include <cuda_fp16.h>
#include <cstdint>
#include <math.h>

#define BATCH 64
#define CH    512
#define NPIX  256
#define HEADS 8
#define HD    64

// Preconverted operands / intermediates (no cudaMalloc allowed) -------------
__device__ uint32_t g_wqh[1536 * 256], g_wql[1536 * 256];   // qkv_w hi/lo fp16 pairs
__device__ uint32_t g_woh[512 * 256],  g_wol[512 * 256];    // out_w hi/lo
__device__ uint32_t g_xt[(size_t)BATCH * NPIX * 256];       // x^T fp16 [b][p][c]
__device__ uint32_t g_qh[(size_t)BATCH * 512 * 128];        // Q hi [b][d][tok-pairs]
__device__ uint32_t g_ql[(size_t)BATCH * 512 * 128];        // Q lo
__device__ uint32_t g_kv[(size_t)BATCH * 1024 * 128];       // K,V fp16
__device__ uint32_t g_att16[(size_t)BATCH * NPIX * 256];    // O^T fp16 [b][p][c]

// ======================= helpers ==========================================
__device__ __forceinline__ uint32_t smem_to_u32(const void* p) {
    uint32_t a;
    asm("{ .reg .u64 t; cvta.to.shared.u64 t, %1; cvt.u32.u64 %0, t; }"
        : "=r"(a) : "l"(p));
    return a;
}
__device__ __forceinline__ uint32_t h2u(__half2 h) {
    return *reinterpret_cast<uint32_t*>(&h);
}
__device__ __forceinline__ void ldm_x4(uint32_t* r, uint32_t addr) {
    asm volatile("ldmatrix.sync.aligned.m8n8.x4.shared.b16 {%0,%1,%2,%3}, [%4];"
        : "=r"(r[0]), "=r"(r[1]), "=r"(r[2]), "=r"(r[3]) : "r"(addr));
}
__device__ __forceinline__ void ldm_x4_t(uint32_t* r, uint32_t addr) {
    asm volatile("ldmatrix.sync.aligned.m8n8.x4.trans.shared.b16 {%0,%1,%2,%3}, [%4];"
        : "=r"(r[0]), "=r"(r[1]), "=r"(r[2]), "=r"(r[3]) : "r"(addr));
}
__device__ __forceinline__ void mma_f16(float* c, const uint32_t* a,
                                        const uint32_t* b) {
    asm volatile(
        "mma.sync.aligned.m16n8k16.row.col.f32.f16.f16.f32 "
        "{%0,%1,%2,%3}, {%4,%5,%6,%7}, {%8,%9}, {%0,%1,%2,%3};"
        : "+f"(c[0]), "+f"(c[1]), "+f"(c[2]), "+f"(c[3])
        : "r"(a[0]), "r"(a[1]), "r"(a[2]), "r"(a[3]), "r"(b[0]), "r"(b[1]));
}
#define CP16(smem, gptr) \
    asm volatile("cp.async.ca.shared.global [%0], [%1], 16;" \
        :: "r"((uint32_t)(smem)), "l"(gptr) : "memory")
#define CP_COMMIT() asm volatile("cp.async.commit_group;" ::: "memory")
#define CP_WAIT(n)  asm volatile("cp.async.wait_group %0;" :: "n"(n) : "memory")

// exp via FMA pipe, |relerr|<3e-6
__device__ __forceinline__ float fast_exp(float t) {
    float y = t * 1.4426950408889634f;
    y = fmaxf(y, -126.0f);
    int ni = __float2int_rn(y);
    float f = y - (float)ni;
    float p = 1.3333558146428443e-3f;
    p = fmaf(p, f, 9.618129842071803e-3f);
    p = fmaf(p, f, 5.550410866482158e-2f);
    p = fmaf(p, f, 2.402265069591007e-1f);
    p = fmaf(p, f, 6.931471805599453e-1f);
    p = fmaf(p, f, 1.0f);
    return __uint_as_float(__float_as_uint(p) + ((uint32_t)ni << 23));
}

// ---------------------------------------------------------------------------
// Preconvert kernels
// ---------------------------------------------------------------------------
__global__ void convert_w(const float* __restrict__ w, uint32_t* __restrict__ wh,
                          uint32_t* __restrict__ wl, int n) {
    int i = blockIdx.x * 256 + threadIdx.x;
    if (i < n) {
        float2 v = ((const float2*)w)[i];
        __half2 h = __floats2half2_rn(v.x, v.y);
        float2 fh = __half22float2(h);
        __half2 l = __floats2half2_rn(v.x - fh.x, v.y - fh.y);
        wh[i] = h2u(h);
        wl[i] = h2u(l);
    }
}

// x [b][c][p] fp32 -> x^T fp16 [b][p][c] (packed c-pairs)
__global__ __launch_bounds__(256) void convert_x(const float* __restrict__ x,
                                                 uint32_t* __restrict__ xt) {
    __shared__ float t[32][33];
    const int b = blockIdx.z, c0 = blockIdx.y * 32, p0 = blockIdx.x * 32;
    const int tx = threadIdx.x & 31, ty = threadIdx.x >> 5;
    const float* xp = x + ((size_t)b * CH + c0 + ty) * NPIX + p0 + tx;
    #pragma unroll
    for (int i = 0; i < 32; i += 8) t[ty + i][tx] = xp[(size_t)i * NPIX];
    __syncthreads();
    const int p = threadIdx.x >> 3, j0 = threadIdx.x & 7;
    const size_t base = ((size_t)b * NPIX + p0 + p) * 256 + c0 / 2;
    #pragma unroll
    for (int jj = 0; jj < 2; jj++) {
        int j = j0 + jj * 8;
        xt[base + j] = h2u(__floats2half2_rn(t[2 * j][p], t[2 * j + 1][p]));
    }
}

// ---------------------------------------------------------------------------
// GEMM (fp16, A 2-term split, B single): Y = W X + bias
// CTA 64x64, 4 warps (2x2), warp tile 32x32 (R10 exact skeleton).
// k64 fetch granularity: 8 lanes per 128B row -> full-line coalesced LDG.
// Smem rows 144B stride (odd x16B: conflict-free STS + LDSM).
// ---------------------------------------------------------------------------
#define G_AH 0
#define G_AL 9216
#define G_BH 18432
#define GEMM_SMEM_BYTES 27648

template <int M, bool PACK>
__global__ __launch_bounds__(128) void gemm_v13(
    const uint32_t* __restrict__ Ah, const uint32_t* __restrict__ Al,
    const uint32_t* __restrict__ Bt, const float* __restrict__ bias,
    float* __restrict__ Yf)
{
    __shared__ __align__(128) char smem[GEMM_SMEM_BYTES];
    const uint32_t sb = smem_to_u32(smem);

    const int tid = threadIdx.x;
    const int wid = tid >> 5;
    const int lane = tid & 31;
    const int wm = wid >> 1;
    const int wn = wid & 1;
    const int p0 = blockIdx.x * 64;
    const int m0 = blockIdx.y * 64;
    const int b  = blockIdx.z;

    // LDG mapping: 8 lanes cover one full 128B row-chunk; rows lrow+16p.
    const int lrow = tid >> 3;            // 0..15
    const int lcol = (tid & 7) * 16;      // 0..112
    const char* gAh = (const char*)Ah + (size_t)(m0 + lrow) * 1024 + lcol;
    const char* gAl = (const char*)Al + (size_t)(m0 + lrow) * 1024 + lcol;
    const char* gBt = (const char*)Bt + ((size_t)b * NPIX + p0 + lrow) * 1024 + lcol;
    const uint32_t srow = (uint32_t)lrow * 144 + lcol;

    // ldmatrix addressing (144B stride)
    const uint32_t aoff = (uint32_t)(wm * 32 + (lane & 15)) * 144 + (lane >> 4) * 16;
    const int q = lane >> 3;
    const uint32_t boff =
        (uint32_t)(wn * 32 + ((q >> 1) & 1) * 8 + (lane & 7)) * 144 + (q & 1) * 16;

    float acc[2][4][4];
    #pragma unroll
    for (int mi = 0; mi < 2; mi++)
        #pragma unroll
        for (int nj = 0; nj < 4; nj++)
            #pragma unroll
            for (int e = 0; e < 4; e++) acc[mi][nj][e] = 0.f;

    // prologue: prefetch iteration 0 (12 full-line-coalesced LDG.128)
    uint4 rah[4], ral[4], rbh[4];
    #pragma unroll
    for (int p = 0; p < 4; p++) {
        rah[p] = *(const uint4*)(gAh + (size_t)(16 * p) * 1024);
        ral[p] = *(const uint4*)(gAl + (size_t)(16 * p) * 1024);
        rbh[p] = *(const uint4*)(gBt + (size_t)(16 * p) * 1024);
    }

    #pragma unroll 1
    for (int c = 0; c < 8; c++) {
        // ---- STS current k64 chunk ----
        #pragma unroll
        for (int p = 0; p < 4; p++) {
            const uint32_t so = srow + p * 16 * 144;
            *(uint4*)(smem + G_AH + so) = rah[p];
            *(uint4*)(smem + G_AL + so) = ral[p];
            *(uint4*)(smem + G_BH + so) = rbh[p];
        }
        __syncthreads();

        // ---- prefetch next chunk (overlaps mma via scoreboard) ----
        if (c < 7) {
            const size_t go = (size_t)(c + 1) * 128;
            #pragma unroll
            for (int p = 0; p < 4; p++) {
                rah[p] = *(const uint4*)(gAh + (size_t)(16 * p) * 1024 + go);
                ral[p] = *(const uint4*)(gAl + (size_t)(16 * p) * 1024 + go);
                rbh[p] = *(const uint4*)(gBt + (size_t)(16 * p) * 1024 + go);
            }
        }

        // ---- compute: 4 k16-steps ----
        #pragma unroll
        for (int ks = 0; ks < 4; ks++) {
            const uint32_t kb = ks * 32;
            uint32_t ah[2][4], al[2][4], bh[2][4];
            ldm_x4(ah[0], sb + G_AH + aoff + kb);
            ldm_x4(ah[1], sb + G_AH + aoff + kb + 16 * 144);
            ldm_x4(al[0], sb + G_AL + aoff + kb);
            ldm_x4(al[1], sb + G_AL + aoff + kb + 16 * 144);
            ldm_x4(bh[0], sb + G_BH + boff + kb);
            ldm_x4(bh[1], sb + G_BH + boff + kb + 16 * 144);

            #pragma unroll
            for (int mi = 0; mi < 2; mi++)
                #pragma unroll
                for (int nj = 0; nj < 4; nj++) {
                    const uint32_t* bhp = &bh[nj >> 1][(nj & 1) * 2];
                    mma_f16(acc[mi][nj], ah[mi], bhp);
                    mma_f16(acc[mi][nj], al[mi], bhp);
                }
        }
        __syncthreads();
    }

    // ---- epilogue ----
    #pragma unroll
    for (int mi = 0; mi < 2; mi++) {
        const int rr = wm * 32 + mi * 16 + (lane >> 2);
        const int o = m0 + rr;
        const float bv0 = __ldg(&bias[o]);
        const float bv1 = __ldg(&bias[o + 8]);
        if (PACK) {
            const size_t pcol = (size_t)(p0 >> 1) + wn * 16 + (lane & 3);
            if (m0 < 512) {                       // Q rows: split hi/lo
                size_t r0 = ((size_t)b * 512 + o) * 128 + pcol;
                size_t r1 = r0 + 8 * 128;
                #pragma unroll
                for (int nj = 0; nj < 4; nj++) {
                    float v0 = acc[mi][nj][0] + bv0, v1 = acc[mi][nj][1] + bv0;
                    __half2 h = __floats2half2_rn(v0, v1);
                    float2 fh = __half22float2(h);
                    __half2 l = __floats2half2_rn(v0 - fh.x, v1 - fh.y);
                    g_qh[r0 + nj * 4] = h2u(h);
                    g_ql[r0 + nj * 4] = h2u(l);
                    float w0 = acc[mi][nj][2] + bv1, w1 = acc[mi][nj][3] + bv1;
                    __half2 h2 = __floats2half2_rn(w0, w1);
                    float2 fh2 = __half22float2(h2);
                    __half2 l2 = __floats2half2_rn(w0 - fh2.x, w1 - fh2.y);
                    g_qh[r1 + nj * 4] = h2u(h2);
                    g_ql[r1 + nj * 4] = h2u(l2);
                }
            } else {                              // K/V rows: single fp16
                size_t r0 = ((size_t)b * 1024 + (o - 512)) * 128 + pcol;
                size_t r1 = r0 + 8 * 128;
                #pragma unroll
                for (int nj = 0; nj < 4; nj++) {
                    g_kv[r0 + nj * 4] = h2u(
                        __floats2half2_rn(acc[mi][nj][0] + bv0, acc[mi][nj][1] + bv0));
                    g_kv[r1 + nj * 4] = h2u(
                        __floats2half2_rn(acc[mi][nj][2] + bv1, acc[mi][nj][3] + bv1));
                }
            }
        } else {
            float* y0 = Yf + ((size_t)b * M + o) * NPIX + p0 + wn * 32 + (lane & 3) * 2;
            float* y1 = y0 + 8 * NPIX;
            #pragma unroll
            for (int nj = 0; nj < 4; nj++) {
                *(float2*)(y0 + nj * 8) =
                    make_float2(acc[mi][nj][0] + bv0, acc[mi][nj][1] + bv0);
                *(float2*)(y1 + nj * 8) =
                    make_float2(acc[mi][nj][2] + bv1, acc[mi][nj][3] + bv1);
            }
        }
    }
}

// ---------------------------------------------------------------------------
// Attention (fp16 2-term; R12's 2-CTA/SM version, verbatim).
// ---------------------------------------------------------------------------
#define AT_QH   0
#define AT_QL   9216
#define AT_KH   18432
#define AT_VH   52224
#define AT_REL  86016
#define AT_MAXB 89872
#define AT_SUMB 90384
#define AT_RS   90896
#define AT_SMEM 91152

__global__ __launch_bounds__(256, 2) void attn_mma(const float* __restrict__ rel)
{
    extern __shared__ char sm[];
    float* smf = (float*)sm;
    const uint32_t sb = smem_to_u32(sm);

    const int tid  = threadIdx.x;
    const int lane = tid & 31;
    const int wid  = tid >> 5;
    const int wn   = wid & 3;
    const int wm   = wid >> 2;
    const int n0g  = blockIdx.x * 64;
    const int h    = blockIdx.y;
    const int b    = blockIdx.z;

    const char* qhp = (const char*)g_qh + ((size_t)b * 512 + h * 64) * 512;
    const char* qlp = (const char*)g_ql + ((size_t)b * 512 + h * 64) * 512;
    const char* kp  = (const char*)g_kv + ((size_t)b * 1024 + h * 64) * 512;
    const char* vp  = kp + (size_t)512 * 512;

    #pragma unroll
    for (int it = 0; it < 2; it++) {
        int i = tid + it * 256;
        int d = i >> 3, ch = (i & 7) * 16;
        CP16(sb + AT_QH + d * 144 + ch, qhp + d * 512 + n0g * 2 + ch);
        CP16(sb + AT_QL + d * 144 + ch, qlp + d * 512 + n0g * 2 + ch);
    }
    #pragma unroll
    for (int it = 0; it < 8; it++) {
        int i = tid + it * 256;
        int d = i >> 5, ch = (i & 31) * 16;
        CP16(sb + AT_KH + d * 528 + ch, kp + d * 512 + ch);
        CP16(sb + AT_VH + d * 528 + ch, vp + d * 512 + ch);
    }
    CP_COMMIT();
    for (int i = tid; i < 961; i += 256)
        smf[AT_REL / 4 + i] = rel[h * 961 + i];
    CP_WAIT(0);
    __syncthreads();

    float acc[16][4];
    #pragma unroll
    for (int f = 0; f < 16; f++)
        #pragma unroll
        for (int e = 0; e < 4; e++) acc[f][e] = 0.f;

    const uint32_t a_row = ((lane >> 4) & 1) * 8 + (lane & 7);
    const uint32_t a_col = (uint32_t)(wn * 16 + ((lane >> 3) & 1) * 8) * 2;
    const uint32_t b_row = ((lane >> 3) & 1) * 8 + (lane & 7);
    const uint32_t b_col8 = ((lane >> 4) & 1) * 8;

    #pragma unroll
    for (int s = 0; s < 4; s++) {
        uint32_t ah[4], al[4];
        ldm_x4_t(ah, sb + AT_QH + (s * 16 + a_row) * 144 + a_col);
        ldm_x4_t(al, sb + AT_QL + (s * 16 + a_row) * 144 + a_col);
        #pragma unroll
        for (int mg = 0; mg < 8; mg++) {
            const uint32_t mcol = (uint32_t)(wm * 128 + mg * 16 + b_col8) * 2;
            uint32_t bh[4];
            ldm_x4_t(bh, sb + AT_KH + (s * 16 + b_row) * 528 + mcol);
            mma_f16(acc[2 * mg], ah, &bh[0]);
            mma_f16(acc[2 * mg], al, &bh[0]);
            mma_f16(acc[2 * mg + 1], ah, &bh[2]);
            mma_f16(acc[2 * mg + 1], al, &bh[2]);
        }
    }

    const int rq  = lane >> 2;
    const int nr  = n0g + wn * 16 + rq;
    const int nr8 = nr + 8;
    const int nb0 = (nr >> 4) * 31 + (nr & 15) + 480;
    const int nb8 = (nr8 >> 4) * 31 + (nr8 & 15) + 480;
    const float* Rs = smf + AT_REL / 4;

    float mx0 = -1e30f, mx8 = -1e30f;
    #pragma unroll
    for (int f = 0; f < 16; f++) {
        int mc = wm * 128 + f * 8 + (lane & 3) * 2;
        int mi0 = (mc >> 4) * 31 + (mc & 15);
        int mi1 = ((mc + 1) >> 4) * 31 + ((mc + 1) & 15);
        acc[f][0] = fmaf(acc[f][0], 0.125f, Rs[nb0 - mi0]);
        acc[f][1] = fmaf(acc[f][1], 0.125f, Rs[nb0 - mi1]);
        acc[f][2] = fmaf(acc[f][2], 0.125f, Rs[nb8 - mi0]);
        acc[f][3] = fmaf(acc[f][3], 0.125f, Rs[nb8 - mi1]);
        mx0 = fmaxf(mx0, fmaxf(acc[f][0], acc[f][1]));
        mx8 = fmaxf(mx8, fmaxf(acc[f][2], acc[f][3]));
    }
    mx0 = fmaxf(mx0, __shfl_xor_sync(0xFFFFFFFF, mx0, 1));
    mx0 = fmaxf(mx0, __shfl_xor_sync(0xFFFFFFFF, mx0, 2));
    mx8 = fmaxf(mx8, __shfl_xor_sync(0xFFFFFFFF, mx8, 1));
    mx8 = fmaxf(mx8, __shfl_xor_sync(0xFFFFFFFF, mx8, 2));
    float* maxb = smf + AT_MAXB / 4;
    const int row = wn * 16 + rq;
    if ((lane & 3) == 0) {
        maxb[wm * 64 + row]     = mx0;
        maxb[wm * 64 + row + 8] = mx8;
    }
    __syncthreads();
    mx0 = fmaxf(maxb[row],     maxb[64 + row]);
    mx8 = fmaxf(maxb[row + 8], maxb[64 + row + 8]);

    float s0 = 0.f, s8 = 0.f;
    #pragma unroll
    for (int f = 0; f < 16; f++) {
        acc[f][0] = fast_exp(acc[f][0] - mx0);
        acc[f][1] = fast_exp(acc[f][1] - mx0);
        acc[f][2] = fast_exp(acc[f][2] - mx8);
        acc[f][3] = fast_exp(acc[f][3] - mx8);
        s0 += acc[f][0] + acc[f][1];
        s8 += acc[f][2] + acc[f][3];
    }
    s0 += __shfl_xor_sync(0xFFFFFFFF, s0, 1);
    s0 += __shfl_xor_sync(0xFFFFFFFF, s0, 2);
    s8 += __shfl_xor_sync(0xFFFFFFFF, s8, 1);
    s8 += __shfl_xor_sync(0xFFFFFFFF, s8, 2);
    float* sumb = smf + AT_SUMB / 4;
    if ((lane & 3) == 0) {
        sumb[wm * 64 + row]     = s0;
        sumb[wm * 64 + row + 8] = s8;
    }
    __syncthreads();
    if (wm == 0 && (lane & 3) == 0) {
        smf[AT_RS / 4 + row]     = 1.f / (sumb[row] + sumb[64 + row]);
        smf[AT_RS / 4 + row + 8] = 1.f / (sumb[row + 8] + sumb[64 + row + 8]);
    }

    uint32_t ph[16][2], pl[16][2];
    #pragma unroll
    for (int f = 0; f < 16; f++) {
        __half2 h01 = __floats2half2_rn(acc[f][0], acc[f][1]);
        __half2 h23 = __floats2half2_rn(acc[f][2], acc[f][3]);
        float2 f01 = __half22float2(h01), f23 = __half22float2(h23);
        __half2 l01 = __floats2half2_rn(acc[f][0] - f01.x, acc[f][1] - f01.y);
        __half2 l23 = __floats2half2_rn(acc[f][2] - f23.x, acc[f][3] - f23.y);
        ph[f][0] = h2u(h01);
        ph[f][1] = h2u(h23);
        pl[f][0] = h2u(l01);
        pl[f][1] = h2u(l23);
    }

    float oacc[8][4];
    #pragma unroll
    for (int g = 0; g < 8; g++)
        #pragma unroll
        for (int e = 0; e < 4; e++) oacc[g][e] = 0.f;

    const uint32_t v_row = ((lane >> 4) & 1) * 8 + (lane & 7);
    const uint32_t v_colh = ((lane >> 3) & 1) * 16;

    #pragma unroll
    for (int s = 0; s < 8; s++) {
        uint32_t a_h[4] = {ph[2 * s][0], ph[2 * s][1], ph[2 * s + 1][0], ph[2 * s + 1][1]};
        uint32_t a_l[4] = {pl[2 * s][0], pl[2 * s][1], pl[2 * s + 1][0], pl[2 * s + 1][1]};
        const uint32_t vcol = (uint32_t)(wm * 128 + s * 16) * 2 + v_colh;
        #pragma unroll
        for (int dg = 0; dg < 4; dg++) {
            uint32_t bh[4];
            const uint32_t vaddr = (dg * 16 + v_row) * 528 + vcol;
            ldm_x4(bh, sb + AT_VH + vaddr);
            mma_f16(oacc[2 * dg], a_h, &bh[0]);
            mma_f16(oacc[2 * dg], a_l, &bh[0]);
            mma_f16(oacc[2 * dg + 1], a_h, &bh[2]);
            mma_f16(oacc[2 * dg + 1], a_l, &bh[2]);
        }
    }

    float* Osm = smf;                            // [2][64][68] overlay on dead Q+K
    #pragma unroll
    for (int g = 0; g < 8; g++) {
        int d = g * 8 + (lane & 3) * 2;
        float* q0 = Osm + (wm * 64 + d) * 68 + row;
        float* q1 = Osm + (wm * 64 + d + 1) * 68 + row;
        q0[0] = oacc[g][0];
        q1[0] = oacc[g][1];
        q0[8] = oacc[g][2];
        q1[8] = oacc[g][3];
    }
    __syncthreads();

    {
        const int n  = tid >> 2;
        const int dq = tid & 3;
        const float rsv = smf[AT_RS / 4 + n];
        const size_t obase = ((size_t)b * NPIX + n0g + n) * 256 + h * 32 + dq * 8;
        #pragma unroll
        for (int j = 0; j < 8; j++) {
            int d0 = dq * 16 + 2 * j;
            float o0 = (Osm[d0 * 68 + n] + Osm[(64 + d0) * 68 + n]) * rsv;
            float o1 = (Osm[(d0 + 1) * 68 + n] + Osm[(64 + d0 + 1) * 68 + n]) * rsv;
            g_att16[obase + j] = h2u(__floats2half2_rn(o0, o1));
        }
    }
}

// ---------------------------------------------------------------------------
extern "C" void kernel_launch(void* const* d_in, const int* in_sizes, int n_in,
                              void* d_out, int out_size)
{
    const float* x      = (const float*)d_in[0];
    const float* qkv_w  = (const float*)d_in[1];
    const float* qkv_b  = (const float*)d_in[2];
    const float* out_w  = (const float*)d_in[3];
    const float* out_b  = (const float*)d_in[4];
    const float* rel    = (const float*)d_in[5];
    float* out = (float*)d_out;

    void *wqh, *wql, *woh, *wol, *xt, *att16;
    cudaGetSymbolAddress(&wqh, g_wqh);
    cudaGetSymbolAddress(&wql, g_wql);
    cudaGetSymbolAddress(&woh, g_woh);
    cudaGetSymbolAddress(&wol, g_wol);
    cudaGetSymbolAddress(&xt, g_xt);
    cudaGetSymbolAddress(&att16, g_att16);

    cudaFuncSetAttribute(attn_mma,
                         cudaFuncAttributeMaxDynamicSharedMemorySize, AT_SMEM);

    // 0) preconvert (tiny)
    convert_w<<<1536, 256>>>(qkv_w, (uint32_t*)wqh, (uint32_t*)wql, 1536 * 256);
    convert_w<<<512, 256>>>(out_w, (uint32_t*)woh, (uint32_t*)wol, 512 * 256);
    convert_x<<<dim3(NPIX / 32, CH / 32, BATCH), 256>>>(x, (uint32_t*)xt);

    // 1) QKV projection -> Q hi/lo + K/V fp16 (attention layout)
    gemm_v13<3 * CH, true><<<dim3(NPIX / 64, 1536 / 64, BATCH), 128>>>(
        (const uint32_t*)wqh, (const uint32_t*)wql, (const uint32_t*)xt,
        qkv_b, nullptr);

    // 2) Attention -> O^T fp16
    attn_mma<<<dim3(NPIX / 64, HEADS, BATCH), 256, AT_SMEM>>>(rel);

    // 3) Output projection -> fp32 (+bias)
    gemm_v13<CH, false><<<dim3(NPIX / 64, CH / 64, BATCH), 128>>>(
        (const uint32_t*)woh, (const uint32_t*)wol, (const uint32_t*)att16,
        out_b, out);
}

// round 14
// speedup vs baseline: 1.7849x; 1.1155x over previous
#include <cuda_runtime.h>
#include <cuda_fp16.h>
#include <cstdint>
#include <math.h>

#define BATCH 64
#define CH    512
#define NPIX  256
#define HEADS 8
#define HD    64

// Preconverted operands / intermediates (no cudaMalloc allowed) -------------
__device__ uint32_t g_wqh[1536 * 256], g_wql[1536 * 256];   // qkv_w hi/lo fp16 pairs
__device__ uint32_t g_woh[512 * 256],  g_wol[512 * 256];    // out_w hi/lo
__device__ uint32_t g_xt[(size_t)BATCH * NPIX * 256];       // x^T fp16 [b][p][c]
__device__ uint32_t g_qh[(size_t)BATCH * 512 * 128];        // Q hi [b][d][tok-pairs]
__device__ uint32_t g_ql[(size_t)BATCH * 512 * 128];        // Q lo
__device__ uint32_t g_kv[(size_t)BATCH * 1024 * 128];       // K,V fp16
__device__ uint32_t g_att16[(size_t)BATCH * NPIX * 256];    // O^T fp16 [b][p][c]

// ======================= helpers ==========================================
__device__ __forceinline__ uint32_t smem_to_u32(const void* p) {
    uint32_t a;
    asm("{ .reg .u64 t; cvta.to.shared.u64 t, %1; cvt.u32.u64 %0, t; }"
        : "=r"(a) : "l"(p));
    return a;
}
__device__ __forceinline__ uint32_t h2u(__half2 h) {
    return *reinterpret_cast<uint32_t*>(&h);
}
__device__ __forceinline__ void ldm_x4(uint32_t* r, uint32_t addr) {
    asm volatile("ldmatrix.sync.aligned.m8n8.x4.shared.b16 {%0,%1,%2,%3}, [%4];"
        : "=r"(r[0]), "=r"(r[1]), "=r"(r[2]), "=r"(r[3]) : "r"(addr));
}
__device__ __forceinline__ void ldm_x4_t(uint32_t* r, uint32_t addr) {
    asm volatile("ldmatrix.sync.aligned.m8n8.x4.trans.shared.b16 {%0,%1,%2,%3}, [%4];"
        : "=r"(r[0]), "=r"(r[1]), "=r"(r[2]), "=r"(r[3]) : "r"(addr));
}
__device__ __forceinline__ void mma_f16(float* c, const uint32_t* a,
                                        const uint32_t* b) {
    asm volatile(
        "mma.sync.aligned.m16n8k16.row.col.f32.f16.f16.f32 "
        "{%0,%1,%2,%3}, {%4,%5,%6,%7}, {%8,%9}, {%0,%1,%2,%3};"
        : "+f"(c[0]), "+f"(c[1]), "+f"(c[2]), "+f"(c[3])
        : "r"(a[0]), "r"(a[1]), "r"(a[2]), "r"(a[3]), "r"(b[0]), "r"(b[1]));
}
#define CP16(smem, gptr) \
    asm volatile("cp.async.ca.shared.global [%0], [%1], 16;" \
        :: "r"((uint32_t)(smem)), "l"(gptr) : "memory")
#define CP_COMMIT() asm volatile("cp.async.commit_group;" ::: "memory")
#define CP_WAIT(n)  asm volatile("cp.async.wait_group %0;" :: "n"(n) : "memory")

// exp via FMA pipe, |relerr|<3e-6
__device__ __forceinline__ float fast_exp(float t) {
    float y = t * 1.4426950408889634f;
    y = fmaxf(y, -126.0f);
    int ni = __float2int_rn(y);
    float f = y - (float)ni;
    float p = 1.3333558146428443e-3f;
    p = fmaf(p, f, 9.618129842071803e-3f);
    p = fmaf(p, f, 5.550410866482158e-2f);
    p = fmaf(p, f, 2.402265069591007e-1f);
    p = fmaf(p, f, 6.931471805599453e-1f);
    p = fmaf(p, f, 1.0f);
    return __uint_as_float(__float_as_uint(p) + ((uint32_t)ni << 23));
}

// ---------------------------------------------------------------------------
// Preconvert kernels
// ---------------------------------------------------------------------------
__global__ void convert_w(const float* __restrict__ w, uint32_t* __restrict__ wh,
                          uint32_t* __restrict__ wl, int n) {
    int i = blockIdx.x * 256 + threadIdx.x;
    if (i < n) {
        float2 v = ((const float2*)w)[i];
        __half2 h = __floats2half2_rn(v.x, v.y);
        float2 fh = __half22float2(h);
        __half2 l = __floats2half2_rn(v.x - fh.x, v.y - fh.y);
        wh[i] = h2u(h);
        wl[i] = h2u(l);
    }
}

// x [b][c][p] fp32 -> x^T fp16 [b][p][c] (packed c-pairs)
__global__ __launch_bounds__(256) void convert_x(const float* __restrict__ x,
                                                 uint32_t* __restrict__ xt) {
    __shared__ float t[32][33];
    const int b = blockIdx.z, c0 = blockIdx.y * 32, p0 = blockIdx.x * 32;
    const int tx = threadIdx.x & 31, ty = threadIdx.x >> 5;
    const float* xp = x + ((size_t)b * CH + c0 + ty) * NPIX + p0 + tx;
    #pragma unroll
    for (int i = 0; i < 32; i += 8) t[ty + i][tx] = xp[(size_t)i * NPIX];
    __syncthreads();
    const int p = threadIdx.x >> 3, j0 = threadIdx.x & 7;
    const size_t base = ((size_t)b * NPIX + p0 + p) * 256 + c0 / 2;
    #pragma unroll
    for (int jj = 0; jj < 2; jj++) {
        int j = j0 + jj * 8;
        xt[base + j] = h2u(__floats2half2_rn(t[2 * j][p], t[2 * j + 1][p]));
    }
}

// ---------------------------------------------------------------------------
// GEMM (fp16): Y = W X + bias.  R10/R13 skeleton.
// TERMS=2: A 2-term split (hi+lo);  TERMS=1: A single fp16 (ah only).
// OUTMODE: 0 = fp32 out (stride via M), 1 = pack Q hi/lo, 2 = pack KV single.
// CTA 64x64, 4 warps (2x2), warp tile 32x32, k64 fetch, 144B smem rows.
// ---------------------------------------------------------------------------
template <int M, int TERMS, int OUTMODE>
__global__ __launch_bounds__(128) void gemm_v14(
    const uint32_t* __restrict__ Ah, const uint32_t* __restrict__ Al,
    const uint32_t* __restrict__ Bt, const float* __restrict__ bias,
    float* __restrict__ Yf)
{
    constexpr int S_AH = 0;
    constexpr int S_AL = 9216;                       // only if TERMS==2
    constexpr int S_BH = (TERMS == 2) ? 18432 : 9216;
    constexpr int SBYTES = S_BH + 9216;
    __shared__ __align__(128) char smem[SBYTES];
    const uint32_t sb = smem_to_u32(smem);

    const int tid = threadIdx.x;
    const int wid = tid >> 5;
    const int lane = tid & 31;
    const int wm = wid >> 1;
    const int wn = wid & 1;
    const int p0 = blockIdx.x * 64;
    const int m0 = blockIdx.y * 64;
    const int b  = blockIdx.z;

    // LDG mapping: 8 lanes cover one full 128B row-chunk; rows lrow+16p.
    const int lrow = tid >> 3;            // 0..15
    const int lcol = (tid & 7) * 16;      // 0..112
    const char* gAh = (const char*)Ah + (size_t)(m0 + lrow) * 1024 + lcol;
    const char* gAl = (const char*)Al + (size_t)(m0 + lrow) * 1024 + lcol;
    const char* gBt = (const char*)Bt + ((size_t)b * NPIX + p0 + lrow) * 1024 + lcol;
    const uint32_t srow = (uint32_t)lrow * 144 + lcol;

    // ldmatrix addressing (144B stride)
    const uint32_t aoff = (uint32_t)(wm * 32 + (lane & 15)) * 144 + (lane >> 4) * 16;
    const int q = lane >> 3;
    const uint32_t boff =
        (uint32_t)(wn * 32 + ((q >> 1) & 1) * 8 + (lane & 7)) * 144 + (q & 1) * 16;

    float acc[2][4][4];
    #pragma unroll
    for (int mi = 0; mi < 2; mi++)
        #pragma unroll
        for (int nj = 0; nj < 4; nj++)
            #pragma unroll
            for (int e = 0; e < 4; e++) acc[mi][nj][e] = 0.f;

    // prologue: prefetch iteration 0
    uint4 rah[4], ral[4], rbh[4];
    #pragma unroll
    for (int p = 0; p < 4; p++) {
        rah[p] = *(const uint4*)(gAh + (size_t)(16 * p) * 1024);
        if (TERMS == 2)
            ral[p] = *(const uint4*)(gAl + (size_t)(16 * p) * 1024);
        rbh[p] = *(const uint4*)(gBt + (size_t)(16 * p) * 1024);
    }

    #pragma unroll 1
    for (int c = 0; c < 8; c++) {
        // ---- STS current k64 chunk ----
        #pragma unroll
        for (int p = 0; p < 4; p++) {
            const uint32_t so = srow + p * 16 * 144;
            *(uint4*)(smem + S_AH + so) = rah[p];
            if (TERMS == 2)
                *(uint4*)(smem + S_AL + so) = ral[p];
            *(uint4*)(smem + S_BH + so) = rbh[p];
        }
        __syncthreads();

        // ---- prefetch next chunk (overlaps mma via scoreboard) ----
        if (c < 7) {
            const size_t go = (size_t)(c + 1) * 128;
            #pragma unroll
            for (int p = 0; p < 4; p++) {
                rah[p] = *(const uint4*)(gAh + (size_t)(16 * p) * 1024 + go);
                if (TERMS == 2)
                    ral[p] = *(const uint4*)(gAl + (size_t)(16 * p) * 1024 + go);
                rbh[p] = *(const uint4*)(gBt + (size_t)(16 * p) * 1024 + go);
            }
        }

        // ---- compute: 4 k16-steps ----
        #pragma unroll
        for (int ks = 0; ks < 4; ks++) {
            const uint32_t kb = ks * 32;
            uint32_t ah[2][4], al[2][4], bh[2][4];
            ldm_x4(ah[0], sb + S_AH + aoff + kb);
            ldm_x4(ah[1], sb + S_AH + aoff + kb + 16 * 144);
            if (TERMS == 2) {
                ldm_x4(al[0], sb + S_AL + aoff + kb);
                ldm_x4(al[1], sb + S_AL + aoff + kb + 16 * 144);
            }
            ldm_x4(bh[0], sb + S_BH + boff + kb);
            ldm_x4(bh[1], sb + S_BH + boff + kb + 16 * 144);

            #pragma unroll
            for (int mi = 0; mi < 2; mi++)
                #pragma unroll
                for (int nj = 0; nj < 4; nj++) {
                    const uint32_t* bhp = &bh[nj >> 1][(nj & 1) * 2];
                    mma_f16(acc[mi][nj], ah[mi], bhp);
                    if (TERMS == 2)
                        mma_f16(acc[mi][nj], al[mi], bhp);
                }
        }
        __syncthreads();
    }

    // ---- epilogue ----
    #pragma unroll
    for (int mi = 0; mi < 2; mi++) {
        const int rr = wm * 32 + mi * 16 + (lane >> 2);
        const int o = m0 + rr;
        const float bv0 = __ldg(&bias[o]);
        const float bv1 = __ldg(&bias[o + 8]);
        if (OUTMODE == 1) {                       // Q: split hi/lo pack
            const size_t pcol = (size_t)(p0 >> 1) + wn * 16 + (lane & 3);
            size_t r0 = ((size_t)b * 512 + o) * 128 + pcol;
            size_t r1 = r0 + 8 * 128;
            #pragma unroll
            for (int nj = 0; nj < 4; nj++) {
                float v0 = acc[mi][nj][0] + bv0, v1 = acc[mi][nj][1] + bv0;
                __half2 h = __floats2half2_rn(v0, v1);
                float2 fh = __half22float2(h);
                __half2 l = __floats2half2_rn(v0 - fh.x, v1 - fh.y);
                g_qh[r0 + nj * 4] = h2u(h);
                g_ql[r0 + nj * 4] = h2u(l);
                float w0 = acc[mi][nj][2] + bv1, w1 = acc[mi][nj][3] + bv1;
                __half2 h2 = __floats2half2_rn(w0, w1);
                float2 fh2 = __half22float2(h2);
                __half2 l2 = __floats2half2_rn(w0 - fh2.x, w1 - fh2.y);
                g_qh[r1 + nj * 4] = h2u(h2);
                g_ql[r1 + nj * 4] = h2u(l2);
            }
        } else if (OUTMODE == 2) {                // KV: single fp16 pack
            const size_t pcol = (size_t)(p0 >> 1) + wn * 16 + (lane & 3);
            size_t r0 = ((size_t)b * 1024 + o) * 128 + pcol;
            size_t r1 = r0 + 8 * 128;
            #pragma unroll
            for (int nj = 0; nj < 4; nj++) {
                g_kv[r0 + nj * 4] = h2u(
                    __floats2half2_rn(acc[mi][nj][0] + bv0, acc[mi][nj][1] + bv0));
                g_kv[r1 + nj * 4] = h2u(
                    __floats2half2_rn(acc[mi][nj][2] + bv1, acc[mi][nj][3] + bv1));
            }
        } else {                                  // fp32 out
            float* y0 = Yf + ((size_t)b * M + o) * NPIX + p0 + wn * 32 + (lane & 3) * 2;
            float* y1 = y0 + 8 * NPIX;
            #pragma unroll
            for (int nj = 0; nj < 4; nj++) {
                *(float2*)(y0 + nj * 8) =
                    make_float2(acc[mi][nj][0] + bv0, acc[mi][nj][1] + bv0);
                *(float2*)(y1 + nj * 8) =
                    make_float2(acc[mi][nj][2] + bv1, acc[mi][nj][3] + bv1);
            }
        }
    }
}

// ---------------------------------------------------------------------------
// Attention (fp16 2-term; R12/R13's 2-CTA/SM version, verbatim).
// ---------------------------------------------------------------------------
#define AT_QH   0
#define AT_QL   9216
#define AT_KH   18432
#define AT_VH   52224
#define AT_REL  86016
#define AT_MAXB 89872
#define AT_SUMB 90384
#define AT_RS   90896
#define AT_SMEM 91152

__global__ __launch_bounds__(256, 2) void attn_mma(const float* __restrict__ rel)
{
    extern __shared__ char sm[];
    float* smf = (float*)sm;
    const uint32_t sb = smem_to_u32(sm);

    const int tid  = threadIdx.x;
    const int lane = tid & 31;
    const int wid  = tid >> 5;
    const int wn   = wid & 3;
    const int wm   = wid >> 2;
    const int n0g  = blockIdx.x * 64;
    const int h    = blockIdx.y;
    const int b    = blockIdx.z;

    const char* qhp = (const char*)g_qh + ((size_t)b * 512 + h * 64) * 512;
    const char* qlp = (const char*)g_ql + ((size_t)b * 512 + h * 64) * 512;
    const char* kp  = (const char*)g_kv + ((size_t)b * 1024 + h * 64) * 512;
    const char* vp  = kp + (size_t)512 * 512;

    #pragma unroll
    for (int it = 0; it < 2; it++) {
        int i = tid + it * 256;
        int d = i >> 3, ch = (i & 7) * 16;
        CP16(sb + AT_QH + d * 144 + ch, qhp + d * 512 + n0g * 2 + ch);
        CP16(sb + AT_QL + d * 144 + ch, qlp + d * 512 + n0g * 2 + ch);
    }
    #pragma unroll
    for (int it = 0; it < 8; it++) {
        int i = tid + it * 256;
        int d = i >> 5, ch = (i & 31) * 16;
        CP16(sb + AT_KH + d * 528 + ch, kp + d * 512 + ch);
        CP16(sb + AT_VH + d * 528 + ch, vp + d * 512 + ch);
    }
    CP_COMMIT();
    for (int i = tid; i < 961; i += 256)
        smf[AT_REL / 4 + i] = rel[h * 961 + i];
    CP_WAIT(0);
    __syncthreads();

    float acc[16][4];
    #pragma unroll
    for (int f = 0; f < 16; f++)
        #pragma unroll
        for (int e = 0; e < 4; e++) acc[f][e] = 0.f;

    const uint32_t a_row = ((lane >> 4) & 1) * 8 + (lane & 7);
    const uint32_t a_col = (uint32_t)(wn * 16 + ((lane >> 3) & 1) * 8) * 2;
    const uint32_t b_row = ((lane >> 3) & 1) * 8 + (lane & 7);
    const uint32_t b_col8 = ((lane >> 4) & 1) * 8;

    #pragma unroll
    for (int s = 0; s < 4; s++) {
        uint32_t ah[4], al[4];
        ldm_x4_t(ah, sb + AT_QH + (s * 16 + a_row) * 144 + a_col);
        ldm_x4_t(al, sb + AT_QL + (s * 16 + a_row) * 144 + a_col);
        #pragma unroll
        for (int mg = 0; mg < 8; mg++) {
            const uint32_t mcol = (uint32_t)(wm * 128 + mg * 16 + b_col8) * 2;
            uint32_t bh[4];
            ldm_x4_t(bh, sb + AT_KH + (s * 16 + b_row) * 528 + mcol);
            mma_f16(acc[2 * mg], ah, &bh[0]);
            mma_f16(acc[2 * mg], al, &bh[0]);
            mma_f16(acc[2 * mg + 1], ah, &bh[2]);
            mma_f16(acc[2 * mg + 1], al, &bh[2]);
        }
    }

    const int rq  = lane >> 2;
    const int nr  = n0g + wn * 16 + rq;
    const int nr8 = nr + 8;
    const int nb0 = (nr >> 4) * 31 + (nr & 15) + 480;
    const int nb8 = (nr8 >> 4) * 31 + (nr8 & 15) + 480;
    const float* Rs = smf + AT_REL / 4;

    float mx0 = -1e30f, mx8 = -1e30f;
    #pragma unroll
    for (int f = 0; f < 16; f++) {
        int mc = wm * 128 + f * 8 + (lane & 3) * 2;
        int mi0 = (mc >> 4) * 31 + (mc & 15);
        int mi1 = ((mc + 1) >> 4) * 31 + ((mc + 1) & 15);
        acc[f][0] = fmaf(acc[f][0], 0.125f, Rs[nb0 - mi0]);
        acc[f][1] = fmaf(acc[f][1], 0.125f, Rs[nb0 - mi1]);
        acc[f][2] = fmaf(acc[f][2], 0.125f, Rs[nb8 - mi0]);
        acc[f][3] = fmaf(acc[f][3], 0.125f, Rs[nb8 - mi1]);
        mx0 = fmaxf(mx0, fmaxf(acc[f][0], acc[f][1]));
        mx8 = fmaxf(mx8, fmaxf(acc[f][2], acc[f][3]));
    }
    mx0 = fmaxf(mx0, __shfl_xor_sync(0xFFFFFFFF, mx0, 1));
    mx0 = fmaxf(mx0, __shfl_xor_sync(0xFFFFFFFF, mx0, 2));
    mx8 = fmaxf(mx8, __shfl_xor_sync(0xFFFFFFFF, mx8, 1));
    mx8 = fmaxf(mx8, __shfl_xor_sync(0xFFFFFFFF, mx8, 2));
    float* maxb = smf + AT_MAXB / 4;
    const int row = wn * 16 + rq;
    if ((lane & 3) == 0) {
        maxb[wm * 64 + row]     = mx0;
        maxb[wm * 64 + row + 8] = mx8;
    }
    __syncthreads();
    mx0 = fmaxf(maxb[row],     maxb[64 + row]);
    mx8 = fmaxf(maxb[row + 8], maxb[64 + row + 8]);

    float s0 = 0.f, s8 = 0.f;
    #pragma unroll
    for (int f = 0; f < 16; f++) {
        acc[f][0] = fast_exp(acc[f][0] - mx0);
        acc[f][1] = fast_exp(acc[f][1] - mx0);
        acc[f][2] = fast_exp(acc[f][2] - mx8);
        acc[f][3] = fast_exp(acc[f][3] - mx8);
        s0 += acc[f][0] + acc[f][1];
        s8 += acc[f][2] + acc[f][3];
    }
    s0 += __shfl_xor_sync(0xFFFFFFFF, s0, 1);
    s0 += __shfl_xor_sync(0xFFFFFFFF, s0, 2);
    s8 += __shfl_xor_sync(0xFFFFFFFF, s8, 1);
    s8 += __shfl_xor_sync(0xFFFFFFFF, s8, 2);
    float* sumb = smf + AT_SUMB / 4;
    if ((lane & 3) == 0) {
        sumb[wm * 64 + row]     = s0;
        sumb[wm * 64 + row + 8] = s8;
    }
    __syncthreads();
    if (wm == 0 && (lane & 3) == 0) {
        smf[AT_RS / 4 + row]     = 1.f / (sumb[row] + sumb[64 + row]);
        smf[AT_RS / 4 + row + 8] = 1.f / (sumb[row + 8] + sumb[64 + row + 8]);
    }

    uint32_t ph[16][2], pl[16][2];
    #pragma unroll
    for (int f = 0; f < 16; f++) {
        __half2 h01 = __floats2half2_rn(acc[f][0], acc[f][1]);
        __half2 h23 = __floats2half2_rn(acc[f][2], acc[f][3]);
        float2 f01 = __half22float2(h01), f23 = __half22float2(h23);
        __half2 l01 = __floats2half2_rn(acc[f][0] - f01.x, acc[f][1] - f01.y);
        __half2 l23 = __floats2half2_rn(acc[f][2] - f23.x, acc[f][3] - f23.y);
        ph[f][0] = h2u(h01);
        ph[f][1] = h2u(h23);
        pl[f][0] = h2u(l01);
        pl[f][1] = h2u(l23);
    }

    float oacc[8][4];
    #pragma unroll
    for (int g = 0; g < 8; g++)
        #pragma unroll
        for (int e = 0; e < 4; e++) oacc[g][e] = 0.f;

    const uint32_t v_row = ((lane >> 4) & 1) * 8 + (lane & 7);
    const uint32_t v_colh = ((lane >> 3) & 1) * 16;

    #pragma unroll
    for (int s = 0; s < 8; s++) {
        uint32_t a_h[4] = {ph[2 * s][0], ph[2 * s][1], ph[2 * s + 1][0], ph[2 * s + 1][1]};
        uint32_t a_l[4] = {pl[2 * s][0], pl[2 * s][1], pl[2 * s + 1][0], pl[2 * s + 1][1]};
        const uint32_t vcol = (uint32_t)(wm * 128 + s * 16) * 2 + v_colh;
        #pragma unroll
        for (int dg = 0; dg < 4; dg++) {
            uint32_t bh[4];
            const uint32_t vaddr = (dg * 16 + v_row) * 528 + vcol;
            ldm_x4(bh, sb + AT_VH + vaddr);
            mma_f16(oacc[2 * dg], a_h, &bh[0]);
            mma_f16(oacc[2 * dg], a_l, &bh[0]);
            mma_f16(oacc[2 * dg + 1], a_h, &bh[2]);
            mma_f16(oacc[2 * dg + 1], a_l, &bh[2]);
        }
    }

    float* Osm = smf;                            // [2][64][68] overlay on dead Q+K
    #pragma unroll
    for (int g = 0; g < 8; g++) {
        int d = g * 8 + (lane & 3) * 2;
        float* q0 = Osm + (wm * 64 + d) * 68 + row;
        float* q1 = Osm + (wm * 64 + d + 1) * 68 + row;
        q0[0] = oacc[g][0];
        q1[0] = oacc[g][1];
        q0[8] = oacc[g][2];
        q1[8] = oacc[g][3];
    }
    __syncthreads();

    {
        const int n  = tid >> 2;
        const int dq = tid & 3;
        const float rsv = smf[AT_RS / 4 + n];
        const size_t obase = ((size_t)b * NPIX + n0g + n) * 256 + h * 32 + dq * 8;
        #pragma unroll
        for (int j = 0; j < 8; j++) {
            int d0 = dq * 16 + 2 * j;
            float o0 = (Osm[d0 * 68 + n] + Osm[(64 + d0) * 68 + n]) * rsv;
            float o1 = (Osm[(d0 + 1) * 68 + n] + Osm[(64 + d0 + 1) * 68 + n]) * rsv;
            g_att16[obase + j] = h2u(__floats2half2_rn(o0, o1));
        }
    }
}

// ---------------------------------------------------------------------------
extern "C" void kernel_launch(void* const* d_in, const int* in_sizes, int n_in,
                              void* d_out, int out_size)
{
    const float* x      = (const float*)d_in[0];
    const float* qkv_w  = (const float*)d_in[1];
    const float* qkv_b  = (const float*)d_in[2];
    const float* out_w  = (const float*)d_in[3];
    const float* out_b  = (const float*)d_in[4];
    const float* rel    = (const float*)d_in[5];
    float* out = (float*)d_out;

    void *wqh, *wql, *woh, *wol, *xt, *att16;
    cudaGetSymbolAddress(&wqh, g_wqh);
    cudaGetSymbolAddress(&wql, g_wql);
    cudaGetSymbolAddress(&woh, g_woh);
    cudaGetSymbolAddress(&wol, g_wol);
    cudaGetSymbolAddress(&xt, g_xt);
    cudaGetSymbolAddress(&att16, g_att16);

    cudaFuncSetAttribute(attn_mma,
                         cudaFuncAttributeMaxDynamicSharedMemorySize, AT_SMEM);

    // 0) preconvert (tiny)
    convert_w<<<1536, 256>>>(qkv_w, (uint32_t*)wqh, (uint32_t*)wql, 1536 * 256);
    convert_w<<<512, 256>>>(out_w, (uint32_t*)woh, (uint32_t*)wol, 512 * 256);
    convert_x<<<dim3(NPIX / 32, CH / 32, BATCH), 256>>>(x, (uint32_t*)xt);

    // 1a) Q projection (rows 0-511): 2-term A -> Q hi/lo
    gemm_v14<512, 2, 1><<<dim3(NPIX / 64, 512 / 64, BATCH), 128>>>(
        (const uint32_t*)wqh, (const uint32_t*)wql, (const uint32_t*)xt,
        qkv_b, nullptr);

    // 1b) K/V projection (rows 512-1535): 1-term A -> KV single fp16
    gemm_v14<1024, 1, 2><<<dim3(NPIX / 64, 1024 / 64, BATCH), 128>>>(
        (const uint32_t*)wqh + 512 * 256, (const uint32_t*)wqh + 512 * 256,
        (const uint32_t*)xt, qkv_b + 512, nullptr);

    // 2) Attention -> O^T fp16
    attn_mma<<<dim3(NPIX / 64, HEADS, BATCH), 256, AT_SMEM>>>(rel);

    // 3) Output projection -> fp32 (+bias, 2-term)
    gemm_v14<512, 2, 0><<<dim3(NPIX / 64, 512 / 64, BATCH), 128>>>(
        (const uint32_t*)woh, (const uint32_t*)wol, (const uint32_t*)att16,
        out_b, out);
}

// round 15
// speedup vs baseline: 1.9165x; 1.0738x over previous
#include <cuda_runtime.h>
#include <cuda_fp16.h>
#include <cstdint>
#include <math.h>

#define BATCH 64
#define CH    512
#define NPIX  256
#define HEADS 8
#define HD    64

// Preconverted operands / intermediates (no cudaMalloc allowed) -------------
__device__ uint32_t g_wqh[1536 * 256], g_wql[1536 * 256];   // qkv_w hi/lo fp16 pairs
__device__ uint32_t g_woh[512 * 256];                       // out_w hi (single)
__device__ uint32_t g_xt[(size_t)BATCH * NPIX * 256];       // x^T fp16 [b][p][c]
__device__ uint32_t g_qh[(size_t)BATCH * 512 * 128];        // Q hi [b][d][tok-pairs]
__device__ uint32_t g_ql[(size_t)BATCH * 512 * 128];        // Q lo
__device__ uint32_t g_kv[(size_t)BATCH * 1024 * 128];       // K,V fp16
__device__ uint32_t g_att16[(size_t)BATCH * NPIX * 256];    // O^T fp16 [b][p][c]

// ======================= helpers ==========================================
__device__ __forceinline__ uint32_t smem_to_u32(const void* p) {
    uint32_t a;
    asm("{ .reg .u64 t; cvta.to.shared.u64 t, %1; cvt.u32.u64 %0, t; }"
        : "=r"(a) : "l"(p));
    return a;
}
__device__ __forceinline__ uint32_t h2u(__half2 h) {
    return *reinterpret_cast<uint32_t*>(&h);
}
__device__ __forceinline__ void ldm_x4(uint32_t* r, uint32_t addr) {
    asm volatile("ldmatrix.sync.aligned.m8n8.x4.shared.b16 {%0,%1,%2,%3}, [%4];"
        : "=r"(r[0]), "=r"(r[1]), "=r"(r[2]), "=r"(r[3]) : "r"(addr));
}
__device__ __forceinline__ void ldm_x4_t(uint32_t* r, uint32_t addr) {
    asm volatile("ldmatrix.sync.aligned.m8n8.x4.trans.shared.b16 {%0,%1,%2,%3}, [%4];"
        : "=r"(r[0]), "=r"(r[1]), "=r"(r[2]), "=r"(r[3]) : "r"(addr));
}
__device__ __forceinline__ void mma_f16(float* c, const uint32_t* a,
                                        const uint32_t* b) {
    asm volatile(
        "mma.sync.aligned.m16n8k16.row.col.f32.f16.f16.f32 "
        "{%0,%1,%2,%3}, {%4,%5,%6,%7}, {%8,%9}, {%0,%1,%2,%3};"
        : "+f"(c[0]), "+f"(c[1]), "+f"(c[2]), "+f"(c[3])
        : "r"(a[0]), "r"(a[1]), "r"(a[2]), "r"(a[3]), "r"(b[0]), "r"(b[1]));
}
#define CP16(smem, gptr) \
    asm volatile("cp.async.ca.shared.global [%0], [%1], 16;" \
        :: "r"((uint32_t)(smem)), "l"(gptr) : "memory")
#define CP_COMMIT() asm volatile("cp.async.commit_group;" ::: "memory")
#define CP_WAIT(n)  asm volatile("cp.async.wait_group %0;" :: "n"(n) : "memory")

// exp via FMA pipe, |relerr|<3e-6
__device__ __forceinline__ float fast_exp(float t) {
    float y = t * 1.4426950408889634f;
    y = fmaxf(y, -126.0f);
    int ni = __float2int_rn(y);
    float f = y - (float)ni;
    float p = 1.3333558146428443e-3f;
    p = fmaf(p, f, 9.618129842071803e-3f);
    p = fmaf(p, f, 5.550410866482158e-2f);
    p = fmaf(p, f, 2.402265069591007e-1f);
    p = fmaf(p, f, 6.931471805599453e-1f);
    p = fmaf(p, f, 1.0f);
    return __uint_as_float(__float_as_uint(p) + ((uint32_t)ni << 23));
}

// ---------------------------------------------------------------------------
// Preconvert kernels
// ---------------------------------------------------------------------------
__global__ void convert_w2(const float* __restrict__ w, uint32_t* __restrict__ wh,
                           uint32_t* __restrict__ wl, int n) {
    int i = blockIdx.x * 256 + threadIdx.x;
    if (i < n) {
        float2 v = ((const float2*)w)[i];
        __half2 h = __floats2half2_rn(v.x, v.y);
        float2 fh = __half22float2(h);
        __half2 l = __floats2half2_rn(v.x - fh.x, v.y - fh.y);
        wh[i] = h2u(h);
        wl[i] = h2u(l);
    }
}
__global__ void convert_w1(const float* __restrict__ w, uint32_t* __restrict__ wh,
                           int n) {
    int i = blockIdx.x * 256 + threadIdx.x;
    if (i < n) {
        float2 v = ((const float2*)w)[i];
        wh[i] = h2u(__floats2half2_rn(v.x, v.y));
    }
}

// x [b][c][p] fp32 -> x^T fp16 [b][p][c] (packed c-pairs)
__global__ __launch_bounds__(256) void convert_x(const float* __restrict__ x,
                                                 uint32_t* __restrict__ xt) {
    __shared__ float t[32][33];
    const int b = blockIdx.z, c0 = blockIdx.y * 32, p0 = blockIdx.x * 32;
    const int tx = threadIdx.x & 31, ty = threadIdx.x >> 5;
    const float* xp = x + ((size_t)b * CH + c0 + ty) * NPIX + p0 + tx;
    #pragma unroll
    for (int i = 0; i < 32; i += 8) t[ty + i][tx] = xp[(size_t)i * NPIX];
    __syncthreads();
    const int p = threadIdx.x >> 3, j0 = threadIdx.x & 7;
    const size_t base = ((size_t)b * NPIX + p0 + p) * 256 + c0 / 2;
    #pragma unroll
    for (int jj = 0; jj < 2; jj++) {
        int j = j0 + jj * 8;
        xt[base + j] = h2u(__floats2half2_rn(t[2 * j][p], t[2 * j + 1][p]));
    }
}

// ---------------------------------------------------------------------------
// GEMM (fp16): Y = W X + bias.  R10/R13 skeleton.
// TERMS=2: A 2-term split (hi+lo);  TERMS=1: A single fp16 (ah only).
// OUTMODE: 0 = fp32 out (stride via M), 1 = pack Q hi/lo, 2 = pack KV single.
// CTA 64x64, 4 warps (2x2), warp tile 32x32, k64 fetch, 144B smem rows.
// ---------------------------------------------------------------------------
template <int M, int TERMS, int OUTMODE>
__global__ __launch_bounds__(128) void gemm_v15(
    const uint32_t* __restrict__ Ah, const uint32_t* __restrict__ Al,
    const uint32_t* __restrict__ Bt, const float* __restrict__ bias,
    float* __restrict__ Yf)
{
    constexpr int S_AH = 0;
    constexpr int S_AL = 9216;                       // only if TERMS==2
    constexpr int S_BH = (TERMS == 2) ? 18432 : 9216;
    constexpr int SBYTES = S_BH + 9216;
    __shared__ __align__(128) char smem[SBYTES];
    const uint32_t sb = smem_to_u32(smem);

    const int tid = threadIdx.x;
    const int wid = tid >> 5;
    const int lane = tid & 31;
    const int wm = wid >> 1;
    const int wn = wid & 1;
    const int p0 = blockIdx.x * 64;
    const int m0 = blockIdx.y * 64;
    const int b  = blockIdx.z;

    // LDG mapping: 8 lanes cover one full 128B row-chunk; rows lrow+16p.
    const int lrow = tid >> 3;            // 0..15
    const int lcol = (tid & 7) * 16;      // 0..112
    const char* gAh = (const char*)Ah + (size_t)(m0 + lrow) * 1024 + lcol;
    const char* gAl = (const char*)Al + (size_t)(m0 + lrow) * 1024 + lcol;
    const char* gBt = (const char*)Bt + ((size_t)b * NPIX + p0 + lrow) * 1024 + lcol;
    const uint32_t srow = (uint32_t)lrow * 144 + lcol;

    // ldmatrix addressing (144B stride)
    const uint32_t aoff = (uint32_t)(wm * 32 + (lane & 15)) * 144 + (lane >> 4) * 16;
    const int q = lane >> 3;
    const uint32_t boff =
        (uint32_t)(wn * 32 + ((q >> 1) & 1) * 8 + (lane & 7)) * 144 + (q & 1) * 16;

    float acc[2][4][4];
    #pragma unroll
    for (int mi = 0; mi < 2; mi++)
        #pragma unroll
        for (int nj = 0; nj < 4; nj++)
            #pragma unroll
            for (int e = 0; e < 4; e++) acc[mi][nj][e] = 0.f;

    // prologue: prefetch iteration 0
    uint4 rah[4], ral[4], rbh[4];
    #pragma unroll
    for (int p = 0; p < 4; p++) {
        rah[p] = *(const uint4*)(gAh + (size_t)(16 * p) * 1024);
        if (TERMS == 2)
            ral[p] = *(const uint4*)(gAl + (size_t)(16 * p) * 1024);
        rbh[p] = *(const uint4*)(gBt + (size_t)(16 * p) * 1024);
    }

    #pragma unroll 1
    for (int c = 0; c < 8; c++) {
        // ---- STS current k64 chunk ----
        #pragma unroll
        for (int p = 0; p < 4; p++) {
            const uint32_t so = srow + p * 16 * 144;
            *(uint4*)(smem + S_AH + so) = rah[p];
            if (TERMS == 2)
                *(uint4*)(smem + S_AL + so) = ral[p];
            *(uint4*)(smem + S_BH + so) = rbh[p];
        }
        __syncthreads();

        // ---- prefetch next chunk (overlaps mma via scoreboard) ----
        if (c < 7) {
            const size_t go = (size_t)(c + 1) * 128;
            #pragma unroll
            for (int p = 0; p < 4; p++) {
                rah[p] = *(const uint4*)(gAh + (size_t)(16 * p) * 1024 + go);
                if (TERMS == 2)
                    ral[p] = *(const uint4*)(gAl + (size_t)(16 * p) * 1024 + go);
                rbh[p] = *(const uint4*)(gBt + (size_t)(16 * p) * 1024 + go);
            }
        }

        // ---- compute: 4 k16-steps ----
        #pragma unroll
        for (int ks = 0; ks < 4; ks++) {
            const uint32_t kb = ks * 32;
            uint32_t ah[2][4], al[2][4], bh[2][4];
            ldm_x4(ah[0], sb + S_AH + aoff + kb);
            ldm_x4(ah[1], sb + S_AH + aoff + kb + 16 * 144);
            if (TERMS == 2) {
                ldm_x4(al[0], sb + S_AL + aoff + kb);
                ldm_x4(al[1], sb + S_AL + aoff + kb + 16 * 144);
            }
            ldm_x4(bh[0], sb + S_BH + boff + kb);
            ldm_x4(bh[1], sb + S_BH + boff + kb + 16 * 144);

            #pragma unroll
            for (int mi = 0; mi < 2; mi++)
                #pragma unroll
                for (int nj = 0; nj < 4; nj++) {
                    const uint32_t* bhp = &bh[nj >> 1][(nj & 1) * 2];
                    mma_f16(acc[mi][nj], ah[mi], bhp);
                    if (TERMS == 2)
                        mma_f16(acc[mi][nj], al[mi], bhp);
                }
        }
        __syncthreads();
    }

    // ---- epilogue ----
    #pragma unroll
    for (int mi = 0; mi < 2; mi++) {
        const int rr = wm * 32 + mi * 16 + (lane >> 2);
        const int o = m0 + rr;
        const float bv0 = __ldg(&bias[o]);
        const float bv1 = __ldg(&bias[o + 8]);
        if (OUTMODE == 1) {                       // Q: split hi/lo pack
            const size_t pcol = (size_t)(p0 >> 1) + wn * 16 + (lane & 3);
            size_t r0 = ((size_t)b * 512 + o) * 128 + pcol;
            size_t r1 = r0 + 8 * 128;
            #pragma unroll
            for (int nj = 0; nj < 4; nj++) {
                float v0 = acc[mi][nj][0] + bv0, v1 = acc[mi][nj][1] + bv0;
                __half2 h = __floats2half2_rn(v0, v1);
                float2 fh = __half22float2(h);
                __half2 l = __floats2half2_rn(v0 - fh.x, v1 - fh.y);
                g_qh[r0 + nj * 4] = h2u(h);
                g_ql[r0 + nj * 4] = h2u(l);
                float w0 = acc[mi][nj][2] + bv1, w1 = acc[mi][nj][3] + bv1;
                __half2 h2 = __floats2half2_rn(w0, w1);
                float2 fh2 = __half22float2(h2);
                __half2 l2 = __floats2half2_rn(w0 - fh2.x, w1 - fh2.y);
                g_qh[r1 + nj * 4] = h2u(h2);
                g_ql[r1 + nj * 4] = h2u(l2);
            }
        } else if (OUTMODE == 2) {                // KV: single fp16 pack
            const size_t pcol = (size_t)(p0 >> 1) + wn * 16 + (lane & 3);
            size_t r0 = ((size_t)b * 1024 + o) * 128 + pcol;
            size_t r1 = r0 + 8 * 128;
            #pragma unroll
            for (int nj = 0; nj < 4; nj++) {
                g_kv[r0 + nj * 4] = h2u(
                    __floats2half2_rn(acc[mi][nj][0] + bv0, acc[mi][nj][1] + bv0));
                g_kv[r1 + nj * 4] = h2u(
                    __floats2half2_rn(acc[mi][nj][2] + bv1, acc[mi][nj][3] + bv1));
            }
        } else {                                  // fp32 out
            float* y0 = Yf + ((size_t)b * M + o) * NPIX + p0 + wn * 32 + (lane & 3) * 2;
            float* y1 = y0 + 8 * NPIX;
            #pragma unroll
            for (int nj = 0; nj < 4; nj++) {
                *(float2*)(y0 + nj * 8) =
                    make_float2(acc[mi][nj][0] + bv0, acc[mi][nj][1] + bv0);
                *(float2*)(y1 + nj * 8) =
                    make_float2(acc[mi][nj][2] + bv1, acc[mi][nj][3] + bv1);
            }
        }
    }
}

// ---------------------------------------------------------------------------
// Attention: fp16, Q 2-term for S; P SINGLE-term for PV (O is fp16 anyway).
// 2 CTAs/SM. Epilogue writes O^T single fp16.
// ---------------------------------------------------------------------------
#define AT_QH   0
#define AT_QL   9216
#define AT_KH   18432
#define AT_VH   52224
#define AT_REL  86016
#define AT_MAXB 89872
#define AT_SUMB 90384
#define AT_RS   90896
#define AT_SMEM 91152

__global__ __launch_bounds__(256, 2) void attn_mma(const float* __restrict__ rel)
{
    extern __shared__ char sm[];
    float* smf = (float*)sm;
    const uint32_t sb = smem_to_u32(sm);

    const int tid  = threadIdx.x;
    const int lane = tid & 31;
    const int wid  = tid >> 5;
    const int wn   = wid & 3;
    const int wm   = wid >> 2;
    const int n0g  = blockIdx.x * 64;
    const int h    = blockIdx.y;
    const int b    = blockIdx.z;

    const char* qhp = (const char*)g_qh + ((size_t)b * 512 + h * 64) * 512;
    const char* qlp = (const char*)g_ql + ((size_t)b * 512 + h * 64) * 512;
    const char* kp  = (const char*)g_kv + ((size_t)b * 1024 + h * 64) * 512;
    const char* vp  = kp + (size_t)512 * 512;

    #pragma unroll
    for (int it = 0; it < 2; it++) {
        int i = tid + it * 256;
        int d = i >> 3, ch = (i & 7) * 16;
        CP16(sb + AT_QH + d * 144 + ch, qhp + d * 512 + n0g * 2 + ch);
        CP16(sb + AT_QL + d * 144 + ch, qlp + d * 512 + n0g * 2 + ch);
    }
    #pragma unroll
    for (int it = 0; it < 8; it++) {
        int i = tid + it * 256;
        int d = i >> 5, ch = (i & 31) * 16;
        CP16(sb + AT_KH + d * 528 + ch, kp + d * 512 + ch);
        CP16(sb + AT_VH + d * 528 + ch, vp + d * 512 + ch);
    }
    CP_COMMIT();
    for (int i = tid; i < 961; i += 256)
        smf[AT_REL / 4 + i] = rel[h * 961 + i];
    CP_WAIT(0);
    __syncthreads();

    // ---- S = Q^T K (Q 2-term) ------------------------------------------
    float acc[16][4];
    #pragma unroll
    for (int f = 0; f < 16; f++)
        #pragma unroll
        for (int e = 0; e < 4; e++) acc[f][e] = 0.f;

    const uint32_t a_row = ((lane >> 4) & 1) * 8 + (lane & 7);
    const uint32_t a_col = (uint32_t)(wn * 16 + ((lane >> 3) & 1) * 8) * 2;
    const uint32_t b_row = ((lane >> 3) & 1) * 8 + (lane & 7);
    const uint32_t b_col8 = ((lane >> 4) & 1) * 8;

    #pragma unroll
    for (int s = 0; s < 4; s++) {
        uint32_t ah[4], al[4];
        ldm_x4_t(ah, sb + AT_QH + (s * 16 + a_row) * 144 + a_col);
        ldm_x4_t(al, sb + AT_QL + (s * 16 + a_row) * 144 + a_col);
        #pragma unroll
        for (int mg = 0; mg < 8; mg++) {
            const uint32_t mcol = (uint32_t)(wm * 128 + mg * 16 + b_col8) * 2;
            uint32_t bh[4];
            ldm_x4_t(bh, sb + AT_KH + (s * 16 + b_row) * 528 + mcol);
            mma_f16(acc[2 * mg], ah, &bh[0]);
            mma_f16(acc[2 * mg], al, &bh[0]);
            mma_f16(acc[2 * mg + 1], ah, &bh[2]);
            mma_f16(acc[2 * mg + 1], al, &bh[2]);
        }
    }

    const int rq  = lane >> 2;
    const int nr  = n0g + wn * 16 + rq;
    const int nr8 = nr + 8;
    const int nb0 = (nr >> 4) * 31 + (nr & 15) + 480;
    const int nb8 = (nr8 >> 4) * 31 + (nr8 & 15) + 480;
    const float* Rs = smf + AT_REL / 4;

    float mx0 = -1e30f, mx8 = -1e30f;
    #pragma unroll
    for (int f = 0; f < 16; f++) {
        int mc = wm * 128 + f * 8 + (lane & 3) * 2;
        int mi0 = (mc >> 4) * 31 + (mc & 15);
        int mi1 = ((mc + 1) >> 4) * 31 + ((mc + 1) & 15);
        acc[f][0] = fmaf(acc[f][0], 0.125f, Rs[nb0 - mi0]);
        acc[f][1] = fmaf(acc[f][1], 0.125f, Rs[nb0 - mi1]);
        acc[f][2] = fmaf(acc[f][2], 0.125f, Rs[nb8 - mi0]);
        acc[f][3] = fmaf(acc[f][3], 0.125f, Rs[nb8 - mi1]);
        mx0 = fmaxf(mx0, fmaxf(acc[f][0], acc[f][1]));
        mx8 = fmaxf(mx8, fmaxf(acc[f][2], acc[f][3]));
    }
    mx0 = fmaxf(mx0, __shfl_xor_sync(0xFFFFFFFF, mx0, 1));
    mx0 = fmaxf(mx0, __shfl_xor_sync(0xFFFFFFFF, mx0, 2));
    mx8 = fmaxf(mx8, __shfl_xor_sync(0xFFFFFFFF, mx8, 1));
    mx8 = fmaxf(mx8, __shfl_xor_sync(0xFFFFFFFF, mx8, 2));
    float* maxb = smf + AT_MAXB / 4;
    const int row = wn * 16 + rq;
    if ((lane & 3) == 0) {
        maxb[wm * 64 + row]     = mx0;
        maxb[wm * 64 + row + 8] = mx8;
    }
    __syncthreads();
    mx0 = fmaxf(maxb[row],     maxb[64 + row]);
    mx8 = fmaxf(maxb[row + 8], maxb[64 + row + 8]);

    float s0 = 0.f, s8 = 0.f;
    #pragma unroll
    for (int f = 0; f < 16; f++) {
        acc[f][0] = fast_exp(acc[f][0] - mx0);
        acc[f][1] = fast_exp(acc[f][1] - mx0);
        acc[f][2] = fast_exp(acc[f][2] - mx8);
        acc[f][3] = fast_exp(acc[f][3] - mx8);
        s0 += acc[f][0] + acc[f][1];
        s8 += acc[f][2] + acc[f][3];
    }
    s0 += __shfl_xor_sync(0xFFFFFFFF, s0, 1);
    s0 += __shfl_xor_sync(0xFFFFFFFF, s0, 2);
    s8 += __shfl_xor_sync(0xFFFFFFFF, s8, 1);
    s8 += __shfl_xor_sync(0xFFFFFFFF, s8, 2);
    float* sumb = smf + AT_SUMB / 4;
    if ((lane & 3) == 0) {
        sumb[wm * 64 + row]     = s0;
        sumb[wm * 64 + row + 8] = s8;
    }
    __syncthreads();
    if (wm == 0 && (lane & 3) == 0) {
        smf[AT_RS / 4 + row]     = 1.f / (sumb[row] + sumb[64 + row]);
        smf[AT_RS / 4 + row + 8] = 1.f / (sumb[row + 8] + sumb[64 + row + 8]);
    }

    // ---- repack P (unnormalized) into SINGLE fp16 A-fragments -------------
    uint32_t ph[16][2];
    #pragma unroll
    for (int f = 0; f < 16; f++) {
        ph[f][0] = h2u(__floats2half2_rn(acc[f][0], acc[f][1]));
        ph[f][1] = h2u(__floats2half2_rn(acc[f][2], acc[f][3]));
    }

    // ---- O_partial = P V^T (single-term P) ---------------------------------
    float oacc[8][4];
    #pragma unroll
    for (int g = 0; g < 8; g++)
        #pragma unroll
        for (int e = 0; e < 4; e++) oacc[g][e] = 0.f;

    const uint32_t v_row = ((lane >> 4) & 1) * 8 + (lane & 7);
    const uint32_t v_colh = ((lane >> 3) & 1) * 16;

    #pragma unroll
    for (int s = 0; s < 8; s++) {
        uint32_t a_h[4] = {ph[2 * s][0], ph[2 * s][1], ph[2 * s + 1][0], ph[2 * s + 1][1]};
        const uint32_t vcol = (uint32_t)(wm * 128 + s * 16) * 2 + v_colh;
        #pragma unroll
        for (int dg = 0; dg < 4; dg++) {
            uint32_t bh[4];
            const uint32_t vaddr = (dg * 16 + v_row) * 528 + vcol;
            ldm_x4(bh, sb + AT_VH + vaddr);
            mma_f16(oacc[2 * dg], a_h, &bh[0]);
            mma_f16(oacc[2 * dg + 1], a_h, &bh[2]);
        }
    }

    float* Osm = smf;                            // [2][64][68] overlay on dead Q+K
    #pragma unroll
    for (int g = 0; g < 8; g++) {
        int d = g * 8 + (lane & 3) * 2;
        float* q0 = Osm + (wm * 64 + d) * 68 + row;
        float* q1 = Osm + (wm * 64 + d + 1) * 68 + row;
        q0[0] = oacc[g][0];
        q1[0] = oacc[g][1];
        q0[8] = oacc[g][2];
        q1[8] = oacc[g][3];
    }
    __syncthreads();

    {
        const int n  = tid >> 2;
        const int dq = tid & 3;
        const float rsv = smf[AT_RS / 4 + n];
        const size_t obase = ((size_t)b * NPIX + n0g + n) * 256 + h * 32 + dq * 8;
        #pragma unroll
        for (int j = 0; j < 8; j++) {
            int d0 = dq * 16 + 2 * j;
            float o0 = (Osm[d0 * 68 + n] + Osm[(64 + d0) * 68 + n]) * rsv;
            float o1 = (Osm[(d0 + 1) * 68 + n] + Osm[(64 + d0 + 1) * 68 + n]) * rsv;
            g_att16[obase + j] = h2u(__floats2half2_rn(o0, o1));
        }
    }
}

// ---------------------------------------------------------------------------
extern "C" void kernel_launch(void* const* d_in, const int* in_sizes, int n_in,
                              void* d_out, int out_size)
{
    const float* x      = (const float*)d_in[0];
    const float* qkv_w  = (const float*)d_in[1];
    const float* qkv_b  = (const float*)d_in[2];
    const float* out_w  = (const float*)d_in[3];
    const float* out_b  = (const float*)d_in[4];
    const float* rel    = (const float*)d_in[5];
    float* out = (float*)d_out;

    void *wqh, *wql, *woh, *xt, *att16;
    cudaGetSymbolAddress(&wqh, g_wqh);
    cudaGetSymbolAddress(&wql, g_wql);
    cudaGetSymbolAddress(&woh, g_woh);
    cudaGetSymbolAddress(&xt, g_xt);
    cudaGetSymbolAddress(&att16, g_att16);

    cudaFuncSetAttribute(attn_mma,
                         cudaFuncAttributeMaxDynamicSharedMemorySize, AT_SMEM);

    // 0) preconvert (tiny)
    convert_w2<<<1536, 256>>>(qkv_w, (uint32_t*)wqh, (uint32_t*)wql, 1536 * 256);
    convert_w1<<<512, 256>>>(out_w, (uint32_t*)woh, 512 * 256);
    convert_x<<<dim3(NPIX / 32, CH / 32, BATCH), 256>>>(x, (uint32_t*)xt);

    // 1a) Q projection (rows 0-511): 2-term A -> Q hi/lo
    gemm_v15<512, 2, 1><<<dim3(NPIX / 64, 512 / 64, BATCH), 128>>>(
        (const uint32_t*)wqh, (const uint32_t*)wql, (const uint32_t*)xt,
        qkv_b, nullptr);

    // 1b) K/V projection (rows 512-1535): 1-term A -> KV single fp16
    gemm_v15<1024, 1, 2><<<dim3(NPIX / 64, 1024 / 64, BATCH), 128>>>(
        (const uint32_t*)wqh + 512 * 256, (const uint32_t*)wqh + 512 * 256,
        (const uint32_t*)xt, qkv_b + 512, nullptr);

    // 2) Attention -> O^T fp16 (P single-term in PV)
    attn_mma<<<dim3(NPIX / 64, HEADS, BATCH), 256, AT_SMEM>>>(rel);

    // 3) Output projection -> fp32 (+bias, 1-term W)
    gemm_v15<512, 1, 0><<<dim3(NPIX / 64, 512 / 64, BATCH), 128>>>(
        (const uint32_t*)woh, (const uint32_t*)woh, (const uint32_t*)att16,
        out_b, out);
}

// round 16
// speedup vs baseline: 1.9548x; 1.0200x over previous
#include <cuda_runtime.h>
#include <cuda_fp16.h>
#include <cstdint>
#include <math.h>

#define BATCH 64
#define CH    512
#define NPIX  256
#define HEADS 8
#define HD    64

// Preconverted operands / intermediates (no cudaMalloc allowed) -------------
__device__ uint32_t g_wqh[1536 * 256], g_wql[1536 * 256];   // qkv_w hi/lo fp16 pairs
__device__ uint32_t g_woh[512 * 256];                       // out_w hi (single)
__device__ uint32_t g_xt[(size_t)BATCH * NPIX * 256];       // x^T fp16 [b][p][c]
__device__ uint32_t g_qh[(size_t)BATCH * 512 * 128];        // Q hi [b][d][tok-pairs]
__device__ uint32_t g_ql[(size_t)BATCH * 512 * 128];        // Q lo
__device__ uint32_t g_kv[(size_t)BATCH * 1024 * 128];       // K,V fp16
__device__ uint32_t g_att16[(size_t)BATCH * NPIX * 256];    // O^T fp16 [b][p][c]

// ======================= helpers ==========================================
__device__ __forceinline__ uint32_t smem_to_u32(const void* p) {
    uint32_t a;
    asm("{ .reg .u64 t; cvta.to.shared.u64 t, %1; cvt.u32.u64 %0, t; }"
        : "=r"(a) : "l"(p));
    return a;
}
__device__ __forceinline__ uint32_t h2u(__half2 h) {
    return *reinterpret_cast<uint32_t*>(&h);
}
__device__ __forceinline__ void ldm_x4(uint32_t* r, uint32_t addr) {
    asm volatile("ldmatrix.sync.aligned.m8n8.x4.shared.b16 {%0,%1,%2,%3}, [%4];"
        : "=r"(r[0]), "=r"(r[1]), "=r"(r[2]), "=r"(r[3]) : "r"(addr));
}
__device__ __forceinline__ void ldm_x4_t(uint32_t* r, uint32_t addr) {
    asm volatile("ldmatrix.sync.aligned.m8n8.x4.trans.shared.b16 {%0,%1,%2,%3}, [%4];"
        : "=r"(r[0]), "=r"(r[1]), "=r"(r[2]), "=r"(r[3]) : "r"(addr));
}
__device__ __forceinline__ void mma_f16(float* c, const uint32_t* a,
                                        const uint32_t* b) {
    asm volatile(
        "mma.sync.aligned.m16n8k16.row.col.f32.f16.f16.f32 "
        "{%0,%1,%2,%3}, {%4,%5,%6,%7}, {%8,%9}, {%0,%1,%2,%3};"
        : "+f"(c[0]), "+f"(c[1]), "+f"(c[2]), "+f"(c[3])
        : "r"(a[0]), "r"(a[1]), "r"(a[2]), "r"(a[3]), "r"(b[0]), "r"(b[1]));
}
#define CP16(smem, gptr) \
    asm volatile("cp.async.ca.shared.global [%0], [%1], 16;" \
        :: "r"((uint32_t)(smem)), "l"(gptr) : "memory")
#define CP_COMMIT() asm volatile("cp.async.commit_group;" ::: "memory")
#define CP_WAIT(n)  asm volatile("cp.async.wait_group %0;" :: "n"(n) : "memory")

// exp via FMA pipe, |relerr|<3e-6
__device__ __forceinline__ float fast_exp(float t) {
    float y = t * 1.4426950408889634f;
    y = fmaxf(y, -126.0f);
    int ni = __float2int_rn(y);
    float f = y - (float)ni;
    float p = 1.3333558146428443e-3f;
    p = fmaf(p, f, 9.618129842071803e-3f);
    p = fmaf(p, f, 5.550410866482158e-2f);
    p = fmaf(p, f, 2.402265069591007e-1f);
    p = fmaf(p, f, 6.931471805599453e-1f);
    p = fmaf(p, f, 1.0f);
    return __uint_as_float(__float_as_uint(p) + ((uint32_t)ni << 23));
}

// ---------------------------------------------------------------------------
// Merged preconvert: blocks [0,1536) qkv_w hi/lo; [1536,2048) out_w hi;
// [2048,10240) x transpose+convert.
// ---------------------------------------------------------------------------
__global__ __launch_bounds__(256) void convert_all(
    const float* __restrict__ x, const float* __restrict__ qkv_w,
    const float* __restrict__ out_w, uint32_t* __restrict__ xt,
    uint32_t* __restrict__ wqh, uint32_t* __restrict__ wql,
    uint32_t* __restrict__ woh)
{
    __shared__ float t[32][33];
    const int blk = blockIdx.x;
    if (blk < 1536) {
        int i = blk * 256 + threadIdx.x;
        float2 v = ((const float2*)qkv_w)[i];
        __half2 h = __floats2half2_rn(v.x, v.y);
        float2 fh = __half22float2(h);
        __half2 l = __floats2half2_rn(v.x - fh.x, v.y - fh.y);
        wqh[i] = h2u(h);
        wql[i] = h2u(l);
    } else if (blk < 2048) {
        int i = (blk - 1536) * 256 + threadIdx.x;
        float2 v = ((const float2*)out_w)[i];
        woh[i] = h2u(__floats2half2_rn(v.x, v.y));
    } else {
        const int r = blk - 2048;
        const int b = r >> 7;
        const int rem = r & 127;
        const int c0 = (rem >> 3) * 32;
        const int p0 = (rem & 7) * 32;
        const int tx = threadIdx.x & 31, ty = threadIdx.x >> 5;
        const float* xp = x + ((size_t)b * CH + c0 + ty) * NPIX + p0 + tx;
        #pragma unroll
        for (int i = 0; i < 32; i += 8) t[ty + i][tx] = xp[(size_t)i * NPIX];
        __syncthreads();
        const int p = threadIdx.x >> 3, j0 = threadIdx.x & 7;
        const size_t base = ((size_t)b * NPIX + p0 + p) * 256 + c0 / 2;
        #pragma unroll
        for (int jj = 0; jj < 2; jj++) {
            int j = j0 + jj * 8;
            xt[base + j] = h2u(__floats2half2_rn(t[2 * j][p], t[2 * j + 1][p]));
        }
    }
}

// ---------------------------------------------------------------------------
// GEMM body (fp16): Y = W X + bias.  R13/R15 proven skeleton.
// TERMS=2: A 2-term split; TERMS=1: A single fp16.
// OUTMODE: 0 = fp32 out, 1 = pack Q hi/lo, 2 = pack KV single.
// CTA 64x64, 4 warps (2x2), warp tile 32x32, k64 fetch, 144B smem rows.
// ---------------------------------------------------------------------------
template <int TERMS, int OUTMODE, int S_AL, int S_BH, int M>
__device__ __forceinline__ void gemm_body(
    char* smem, const uint32_t* __restrict__ Ah,
    const uint32_t* __restrict__ Al, const uint32_t* __restrict__ Bt,
    const float* __restrict__ bias, float* __restrict__ Yf, const int m0)
{
    constexpr int S_AH = 0;
    const uint32_t sb = smem_to_u32(smem);

    const int tid = threadIdx.x;
    const int wid = tid >> 5;
    const int lane = tid & 31;
    const int wm = wid >> 1;
    const int wn = wid & 1;
    const int p0 = blockIdx.x * 64;
    const int b  = blockIdx.z;

    // LDG mapping: 8 lanes cover one full 128B row-chunk; rows lrow+16p.
    const int lrow = tid >> 3;            // 0..15
    const int lcol = (tid & 7) * 16;      // 0..112
    const char* gAh = (const char*)Ah + (size_t)(m0 + lrow) * 1024 + lcol;
    const char* gAl = (const char*)Al + (size_t)(m0 + lrow) * 1024 + lcol;
    const char* gBt = (const char*)Bt + ((size_t)b * NPIX + p0 + lrow) * 1024 + lcol;
    const uint32_t srow = (uint32_t)lrow * 144 + lcol;

    // ldmatrix addressing (144B stride)
    const uint32_t aoff = (uint32_t)(wm * 32 + (lane & 15)) * 144 + (lane >> 4) * 16;
    const int q = lane >> 3;
    const uint32_t boff =
        (uint32_t)(wn * 32 + ((q >> 1) & 1) * 8 + (lane & 7)) * 144 + (q & 1) * 16;

    float acc[2][4][4];
    #pragma unroll
    for (int mi = 0; mi < 2; mi++)
        #pragma unroll
        for (int nj = 0; nj < 4; nj++)
            #pragma unroll
            for (int e = 0; e < 4; e++) acc[mi][nj][e] = 0.f;

    // prologue: prefetch iteration 0
    uint4 rah[4], ral[4], rbh[4];
    #pragma unroll
    for (int p = 0; p < 4; p++) {
        rah[p] = *(const uint4*)(gAh + (size_t)(16 * p) * 1024);
        if (TERMS == 2)
            ral[p] = *(const uint4*)(gAl + (size_t)(16 * p) * 1024);
        rbh[p] = *(const uint4*)(gBt + (size_t)(16 * p) * 1024);
    }

    #pragma unroll 1
    for (int c = 0; c < 8; c++) {
        // ---- STS current k64 chunk ----
        #pragma unroll
        for (int p = 0; p < 4; p++) {
            const uint32_t so = srow + p * 16 * 144;
            *(uint4*)(smem + S_AH + so) = rah[p];
            if (TERMS == 2)
                *(uint4*)(smem + S_AL + so) = ral[p];
            *(uint4*)(smem + S_BH + so) = rbh[p];
        }
        __syncthreads();

        // ---- prefetch next chunk (overlaps mma via scoreboard) ----
        if (c < 7) {
            const size_t go = (size_t)(c + 1) * 128;
            #pragma unroll
            for (int p = 0; p < 4; p++) {
                rah[p] = *(const uint4*)(gAh + (size_t)(16 * p) * 1024 + go);
                if (TERMS == 2)
                    ral[p] = *(const uint4*)(gAl + (size_t)(16 * p) * 1024 + go);
                rbh[p] = *(const uint4*)(gBt + (size_t)(16 * p) * 1024 + go);
            }
        }

        // ---- compute: 4 k16-steps ----
        #pragma unroll
        for (int ks = 0; ks < 4; ks++) {
            const uint32_t kb = ks * 32;
            uint32_t ah[2][4], al[2][4], bh[2][4];
            ldm_x4(ah[0], sb + S_AH + aoff + kb);
            ldm_x4(ah[1], sb + S_AH + aoff + kb + 16 * 144);
            if (TERMS == 2) {
                ldm_x4(al[0], sb + S_AL + aoff + kb);
                ldm_x4(al[1], sb + S_AL + aoff + kb + 16 * 144);
            }
            ldm_x4(bh[0], sb + S_BH + boff + kb);
            ldm_x4(bh[1], sb + S_BH + boff + kb + 16 * 144);

            #pragma unroll
            for (int mi = 0; mi < 2; mi++)
                #pragma unroll
                for (int nj = 0; nj < 4; nj++) {
                    const uint32_t* bhp = &bh[nj >> 1][(nj & 1) * 2];
                    mma_f16(acc[mi][nj], ah[mi], bhp);
                    if (TERMS == 2)
                        mma_f16(acc[mi][nj], al[mi], bhp);
                }
        }
        __syncthreads();
    }

    // ---- epilogue ----
    #pragma unroll
    for (int mi = 0; mi < 2; mi++) {
        const int rr = wm * 32 + mi * 16 + (lane >> 2);
        const int o = m0 + rr;
        const float bv0 = __ldg(&bias[o]);
        const float bv1 = __ldg(&bias[o + 8]);
        if (OUTMODE == 1) {                       // Q: split hi/lo pack
            const size_t pcol = (size_t)(p0 >> 1) + wn * 16 + (lane & 3);
            size_t r0 = ((size_t)b * 512 + o) * 128 + pcol;
            size_t r1 = r0 + 8 * 128;
            #pragma unroll
            for (int nj = 0; nj < 4; nj++) {
                float v0 = acc[mi][nj][0] + bv0, v1 = acc[mi][nj][1] + bv0;
                __half2 h = __floats2half2_rn(v0, v1);
                float2 fh = __half22float2(h);
                __half2 l = __floats2half2_rn(v0 - fh.x, v1 - fh.y);
                g_qh[r0 + nj * 4] = h2u(h);
                g_ql[r0 + nj * 4] = h2u(l);
                float w0 = acc[mi][nj][2] + bv1, w1 = acc[mi][nj][3] + bv1;
                __half2 h2 = __floats2half2_rn(w0, w1);
                float2 fh2 = __half22float2(h2);
                __half2 l2 = __floats2half2_rn(w0 - fh2.x, w1 - fh2.y);
                g_qh[r1 + nj * 4] = h2u(h2);
                g_ql[r1 + nj * 4] = h2u(l2);
            }
        } else if (OUTMODE == 2) {                // KV: single fp16 pack
            const size_t pcol = (size_t)(p0 >> 1) + wn * 16 + (lane & 3);
            size_t r0 = ((size_t)b * 1024 + (o - 512)) * 128 + pcol;
            size_t r1 = r0 + 8 * 128;
            #pragma unroll
            for (int nj = 0; nj < 4; nj++) {
                g_kv[r0 + nj * 4] = h2u(
                    __floats2half2_rn(acc[mi][nj][0] + bv0, acc[mi][nj][1] + bv0));
                g_kv[r1 + nj * 4] = h2u(
                    __floats2half2_rn(acc[mi][nj][2] + bv1, acc[mi][nj][3] + bv1));
            }
        } else {                                  // fp32 out
            float* y0 = Yf + ((size_t)b * M + o) * NPIX + p0 + wn * 32 + (lane & 3) * 2;
            float* y1 = y0 + 8 * NPIX;
            #pragma unroll
            for (int nj = 0; nj < 4; nj++) {
                *(float2*)(y0 + nj * 8) =
                    make_float2(acc[mi][nj][0] + bv0, acc[mi][nj][1] + bv0);
                *(float2*)(y1 + nj * 8) =
                    make_float2(acc[mi][nj][2] + bv1, acc[mi][nj][3] + bv1);
            }
        }
    }
}

// Merged QKV projection: rows <512 -> Q (2-term, hi/lo pack);
// rows >=512 -> K/V (1-term, single pack). One launch, no serialization.
__global__ __launch_bounds__(128) void gemm_qkv(
    const uint32_t* __restrict__ Ah, const uint32_t* __restrict__ Al,
    const uint32_t* __restrict__ Bt, const float* __restrict__ bias)
{
    extern __shared__ char smem[];
    const int m0 = blockIdx.y * 64;
    if (m0 < 512)
        gemm_body<2, 1, 9216, 18432, 512>(smem, Ah, Al, Bt, bias, nullptr, m0);
    else
        gemm_body<1, 2, 9216, 18432, 1024>(smem, Ah, Ah, Bt, bias, nullptr, m0);
}

// Output projection: 1-term W, fp32 out.
__global__ __launch_bounds__(128) void gemm_out(
    const uint32_t* __restrict__ Ah, const uint32_t* __restrict__ Bt,
    const float* __restrict__ bias, float* __restrict__ Yf)
{
    extern __shared__ char smem[];
    gemm_body<1, 0, 0, 9216, 512>(smem, Ah, Ah, Bt, bias, Yf, blockIdx.y * 64);
}

// ---------------------------------------------------------------------------
// Attention: fp16, Q 2-term for S; P single-term for PV. 2 CTAs/SM.
// ---------------------------------------------------------------------------
#define AT_QH   0
#define AT_QL   9216
#define AT_KH   18432
#define AT_VH   52224
#define AT_REL  86016
#define AT_MAXB 89872
#define AT_SUMB 90384
#define AT_RS   90896
#define AT_SMEM 91152

__global__ __launch_bounds__(256, 2) void attn_mma(const float* __restrict__ rel)
{
    extern __shared__ char sm[];
    float* smf = (float*)sm;
    const uint32_t sb = smem_to_u32(sm);

    const int tid  = threadIdx.x;
    const int lane = tid & 31;
    const int wid  = tid >> 5;
    const int wn   = wid & 3;
    const int wm   = wid >> 2;
    const int n0g  = blockIdx.x * 64;
    const int h    = blockIdx.y;
    const int b    = blockIdx.z;

    const char* qhp = (const char*)g_qh + ((size_t)b * 512 + h * 64) * 512;
    const char* qlp = (const char*)g_ql + ((size_t)b * 512 + h * 64) * 512;
    const char* kp  = (const char*)g_kv + ((size_t)b * 1024 + h * 64) * 512;
    const char* vp  = kp + (size_t)512 * 512;

    #pragma unroll
    for (int it = 0; it < 2; it++) {
        int i = tid + it * 256;
        int d = i >> 3, ch = (i & 7) * 16;
        CP16(sb + AT_QH + d * 144 + ch, qhp + d * 512 + n0g * 2 + ch);
        CP16(sb + AT_QL + d * 144 + ch, qlp + d * 512 + n0g * 2 + ch);
    }
    #pragma unroll
    for (int it = 0; it < 8; it++) {
        int i = tid + it * 256;
        int d = i >> 5, ch = (i & 31) * 16;
        CP16(sb + AT_KH + d * 528 + ch, kp + d * 512 + ch);
        CP16(sb + AT_VH + d * 528 + ch, vp + d * 512 + ch);
    }
    CP_COMMIT();
    for (int i = tid; i < 961; i += 256)
        smf[AT_REL / 4 + i] = rel[h * 961 + i];
    CP_WAIT(0);
    __syncthreads();

    // ---- S = Q^T K (Q 2-term) ------------------------------------------
    float acc[16][4];
    #pragma unroll
    for (int f = 0; f < 16; f++)
        #pragma unroll
        for (int e = 0; e < 4; e++) acc[f][e] = 0.f;

    const uint32_t a_row = ((lane >> 4) & 1) * 8 + (lane & 7);
    const uint32_t a_col = (uint32_t)(wn * 16 + ((lane >> 3) & 1) * 8) * 2;
    const uint32_t b_row = ((lane >> 3) & 1) * 8 + (lane & 7);
    const uint32_t b_col8 = ((lane >> 4) & 1) * 8;

    #pragma unroll
    for (int s = 0; s < 4; s++) {
        uint32_t ah[4], al[4];
        ldm_x4_t(ah, sb + AT_QH + (s * 16 + a_row) * 144 + a_col);
        ldm_x4_t(al, sb + AT_QL + (s * 16 + a_row) * 144 + a_col);
        #pragma unroll
        for (int mg = 0; mg < 8; mg++) {
            const uint32_t mcol = (uint32_t)(wm * 128 + mg * 16 + b_col8) * 2;
            uint32_t bh[4];
            ldm_x4_t(bh, sb + AT_KH + (s * 16 + b_row) * 528 + mcol);
            mma_f16(acc[2 * mg], ah, &bh[0]);
            mma_f16(acc[2 * mg], al, &bh[0]);
            mma_f16(acc[2 * mg + 1], ah, &bh[2]);
            mma_f16(acc[2 * mg + 1], al, &bh[2]);
        }
    }

    const int rq  = lane >> 2;
    const int nr  = n0g + wn * 16 + rq;
    const int nr8 = nr + 8;
    const int nb0 = (nr >> 4) * 31 + (nr & 15) + 480;
    const int nb8 = (nr8 >> 4) * 31 + (nr8 & 15) + 480;
    const float* Rs = smf + AT_REL / 4;

    float mx0 = -1e30f, mx8 = -1e30f;
    #pragma unroll
    for (int f = 0; f < 16; f++) {
        int mc = wm * 128 + f * 8 + (lane & 3) * 2;
        int mi0 = (mc >> 4) * 31 + (mc & 15);
        int mi1 = ((mc + 1) >> 4) * 31 + ((mc + 1) & 15);
        acc[f][0] = fmaf(acc[f][0], 0.125f, Rs[nb0 - mi0]);
        acc[f][1] = fmaf(acc[f][1], 0.125f, Rs[nb0 - mi1]);
        acc[f][2] = fmaf(acc[f][2], 0.125f, Rs[nb8 - mi0]);
        acc[f][3] = fmaf(acc[f][3], 0.125f, Rs[nb8 - mi1]);
        mx0 = fmaxf(mx0, fmaxf(acc[f][0], acc[f][1]));
        mx8 = fmaxf(mx8, fmaxf(acc[f][2], acc[f][3]));
    }
    mx0 = fmaxf(mx0, __shfl_xor_sync(0xFFFFFFFF, mx0, 1));
    mx0 = fmaxf(mx0, __shfl_xor_sync(0xFFFFFFFF, mx0, 2));
    mx8 = fmaxf(mx8, __shfl_xor_sync(0xFFFFFFFF, mx8, 1));
    mx8 = fmaxf(mx8, __shfl_xor_sync(0xFFFFFFFF, mx8, 2));
    float* maxb = smf + AT_MAXB / 4;
    const int row = wn * 16 + rq;
    if ((lane & 3) == 0) {
        maxb[wm * 64 + row]     = mx0;
        maxb[wm * 64 + row + 8] = mx8;
    }
    __syncthreads();
    mx0 = fmaxf(maxb[row],     maxb[64 + row]);
    mx8 = fmaxf(maxb[row + 8], maxb[64 + row + 8]);

    float s0 = 0.f, s8 = 0.f;
    #pragma unroll
    for (int f = 0; f < 16; f++) {
        acc[f][0] = fast_exp(acc[f][0] - mx0);
        acc[f][1] = fast_exp(acc[f][1] - mx0);
        acc[f][2] = fast_exp(acc[f][2] - mx8);
        acc[f][3] = fast_exp(acc[f][3] - mx8);
        s0 += acc[f][0] + acc[f][1];
        s8 += acc[f][2] + acc[f][3];
    }
    s0 += __shfl_xor_sync(0xFFFFFFFF, s0, 1);
    s0 += __shfl_xor_sync(0xFFFFFFFF, s0, 2);
    s8 += __shfl_xor_sync(0xFFFFFFFF, s8, 1);
    s8 += __shfl_xor_sync(0xFFFFFFFF, s8, 2);
    float* sumb = smf + AT_SUMB / 4;
    if ((lane & 3) == 0) {
        sumb[wm * 64 + row]     = s0;
        sumb[wm * 64 + row + 8] = s8;
    }
    __syncthreads();
    if (wm == 0 && (lane & 3) == 0) {
        smf[AT_RS / 4 + row]     = 1.f / (sumb[row] + sumb[64 + row]);
        smf[AT_RS / 4 + row + 8] = 1.f / (sumb[row + 8] + sumb[64 + row + 8]);
    }

    // ---- repack P into single fp16 A-fragments -----------------------------
    uint32_t ph[16][2];
    #pragma unroll
    for (int f = 0; f < 16; f++) {
        ph[f][0] = h2u(__floats2half2_rn(acc[f][0], acc[f][1]));
        ph[f][1] = h2u(__floats2half2_rn(acc[f][2], acc[f][3]));
    }

    // ---- O_partial = P V^T (single-term P) ---------------------------------
    float oacc[8][4];
    #pragma unroll
    for (int g = 0; g < 8; g++)
        #pragma unroll
        for (int e = 0; e < 4; e++) oacc[g][e] = 0.f;

    const uint32_t v_row = ((lane >> 4) & 1) * 8 + (lane & 7);
    const uint32_t v_colh = ((lane >> 3) & 1) * 16;

    #pragma unroll
    for (int s = 0; s < 8; s++) {
        uint32_t a_h[4] = {ph[2 * s][0], ph[2 * s][1], ph[2 * s + 1][0], ph[2 * s + 1][1]};
        const uint32_t vcol = (uint32_t)(wm * 128 + s * 16) * 2 + v_colh;
        #pragma unroll
        for (int dg = 0; dg < 4; dg++) {
            uint32_t bh[4];
            const uint32_t vaddr = (dg * 16 + v_row) * 528 + vcol;
            ldm_x4(bh, sb + AT_VH + vaddr);
            mma_f16(oacc[2 * dg], a_h, &bh[0]);
            mma_f16(oacc[2 * dg + 1], a_h, &bh[2]);
        }
    }

    float* Osm = smf;                            // [2][64][68] overlay on dead Q+K
    #pragma unroll
    for (int g = 0; g < 8; g++) {
        int d = g * 8 + (lane & 3) * 2;
        float* q0 = Osm + (wm * 64 + d) * 68 + row;
        float* q1 = Osm + (wm * 64 + d + 1) * 68 + row;
        q0[0] = oacc[g][0];
        q1[0] = oacc[g][1];
        q0[8] = oacc[g][2];
        q1[8] = oacc[g][3];
    }
    __syncthreads();

    {
        const int n  = tid >> 2;
        const int dq = tid & 3;
        const float rsv = smf[AT_RS / 4 + n];
        const size_t obase = ((size_t)b * NPIX + n0g + n) * 256 + h * 32 + dq * 8;
        #pragma unroll
        for (int j = 0; j < 8; j++) {
            int d0 = dq * 16 + 2 * j;
            float o0 = (Osm[d0 * 68 + n] + Osm[(64 + d0) * 68 + n]) * rsv;
            float o1 = (Osm[(d0 + 1) * 68 + n] + Osm[(64 + d0 + 1) * 68 + n]) * rsv;
            g_att16[obase + j] = h2u(__floats2half2_rn(o0, o1));
        }
    }
}

// ---------------------------------------------------------------------------
extern "C" void kernel_launch(void* const* d_in, const int* in_sizes, int n_in,
                              void* d_out, int out_size)
{
    const float* x      = (const float*)d_in[0];
    const float* qkv_w  = (const float*)d_in[1];
    const float* qkv_b  = (const float*)d_in[2];
    const float* out_w  = (const float*)d_in[3];
    const float* out_b  = (const float*)d_in[4];
    const float* rel    = (const float*)d_in[5];
    float* out = (float*)d_out;

    void *wqh, *wql, *woh, *xt, *att16;
    cudaGetSymbolAddress(&wqh, g_wqh);
    cudaGetSymbolAddress(&wql, g_wql);
    cudaGetSymbolAddress(&woh, g_woh);
    cudaGetSymbolAddress(&xt, g_xt);
    cudaGetSymbolAddress(&att16, g_att16);

    cudaFuncSetAttribute(attn_mma,
                         cudaFuncAttributeMaxDynamicSharedMemorySize, AT_SMEM);

    // 0) merged preconvert (one launch)
    convert_all<<<10240, 256>>>(x, qkv_w, out_w, (uint32_t*)xt,
                                (uint32_t*)wqh, (uint32_t*)wql, (uint32_t*)woh);

    // 1) merged QKV projection: Q (2-term) + K/V (1-term) in one grid
    gemm_qkv<<<dim3(NPIX / 64, 1536 / 64, BATCH), 128, 27648>>>(
        (const uint32_t*)wqh, (const uint32_t*)wql, (const uint32_t*)xt, qkv_b);

    // 2) Attention -> O^T fp16
    attn_mma<<<dim3(NPIX / 64, HEADS, BATCH), 256, AT_SMEM>>>(rel);

    // 3) Output projection -> fp32 (+bias, 1-term W)
    gemm_out<<<dim3(NPIX / 64, 512 / 64, BATCH), 128, 18432>>>(
        (const uint32_t*)woh, (const uint32_t*)att16, out_b, out);
}